// round 10
// baseline (speedup 1.0000x reference)
#include <cuda_runtime.h>
#include <cuda_fp16.h>
#include <cstdint>
#include <math.h>

#define T_TOKENS 8192
#define H_DIM    512
#define I_DIM    1024
#define E_NUM    8
#define CAP      T_TOKENS                // per-expert capacity
#define KC       64                      // K elems per stage (128B rows)

// ---------------- smem layout -------------------------------------------------
// per stage: 2 tiles (A, B), each 128 rows x 64 fp16, row stride 144B.
#define ROWB      144
#define TILE_SZ   (128 * ROWB)           // 18432 B
#define OFF_A     0
#define OFF_B     TILE_SZ
#define STG_BYTES (2 * TILE_SZ)          // 36864 B
#define NSTAGE    3
#define SMEM_BYTES (NSTAGE * STG_BYTES)  // 110592 B -> 2 CTAs/SM (221 KB < 228 KB)

// ---------------- PTX helpers ---------------------------------------------------
__device__ __forceinline__ uint32_t smem_to_u32(const void* p) {
    uint32_t a;
    asm("{ .reg .u64 t; cvta.to.shared.u64 t, %1; cvt.u32.u64 %0, t; }" : "=r"(a) : "l"(p));
    return a;
}
__device__ __forceinline__ void cp16(uint32_t s, const void* g) {
    asm volatile("cp.async.cg.shared.global [%0], [%1], 16;" :: "r"(s), "l"(g));
}
#define CP_COMMIT() asm volatile("cp.async.commit_group;" ::: "memory")
#define CP_WAIT1()  asm volatile("cp.async.wait_group 1;" ::: "memory")
#define CP_WAIT0()  asm volatile("cp.async.wait_group 0;" ::: "memory")

__device__ __forceinline__ void ldsm4(uint32_t* r, uint32_t a) {
    asm volatile("ldmatrix.sync.aligned.m8n8.x4.shared.b16 {%0,%1,%2,%3}, [%4];"
        : "=r"(r[0]), "=r"(r[1]), "=r"(r[2]), "=r"(r[3]) : "r"(a));
}
__device__ __forceinline__ void mma_f16(float* c, const uint32_t* a, const uint32_t* b) {
    asm volatile("mma.sync.aligned.m16n8k16.row.col.f32.f16.f16.f32 "
        "{%0,%1,%2,%3}, {%4,%5,%6,%7}, {%8,%9}, {%0,%1,%2,%3};"
        : "+f"(c[0]), "+f"(c[1]), "+f"(c[2]), "+f"(c[3])
        : "r"(a[0]), "r"(a[1]), "r"(a[2]), "r"(a[3]), "r"(b[0]), "r"(b[1]));
}

// ---------------- scratch (device globals) -------------------------------------
__device__ int   g_count[E_NUM];
__device__ int   g_list_tok[E_NUM * CAP];
__device__ float g_list_w[E_NUM * CAP];

__device__ __half g_xh[(size_t)T_TOKENS * H_DIM];
__device__ __half g_w1t[(size_t)E_NUM * I_DIM * H_DIM];   // [e][n=I][k=H]
__device__ __half g_w2t[(size_t)E_NUM * H_DIM * I_DIM];   // [e][n=H][k=I]
__device__ __half g_h[(size_t)E_NUM * CAP * I_DIM];

// ---------------- tiny zero kernel ----------------------------------------------
__global__ void zero_small_kernel() {
    if (threadIdx.x < E_NUM) g_count[threadIdx.x] = 0;
}

// ------- router (fused: zero out-head, logits, top-2, x->fp16, direct scatter) --
__global__ void router_kernel(const float* __restrict__ x,
                              const float* __restrict__ gw,
                              float* __restrict__ logits_out,
                              float4* __restrict__ out4) {
    int tid = threadIdx.x;
    #pragma unroll
    for (int i = 0; i < 4; i++)
        out4[(size_t)blockIdx.x * 1024 + i * 256 + tid] = make_float4(0.f, 0.f, 0.f, 0.f);

    int warp = tid >> 5, lane = tid & 31;
    int t = blockIdx.x * 8 + warp;

    float xr[16];
    #pragma unroll
    for (int j = 0; j < 16; j++) xr[j] = x[(size_t)t * H_DIM + lane + 32 * j];

    #pragma unroll
    for (int j = 0; j < 16; j++)
        g_xh[(size_t)t * H_DIM + lane + 32 * j] = __float2half_rn(xr[j]);

    float lg[E_NUM];
    #pragma unroll
    for (int e = 0; e < E_NUM; e++) {
        float s = 0.f;
        const float* g = gw + (size_t)e * H_DIM + lane;
        #pragma unroll
        for (int j = 0; j < 16; j++) s = fmaf(xr[j], g[32 * j], s);
        #pragma unroll
        for (int o = 16; o; o >>= 1) s += __shfl_xor_sync(0xffffffffu, s, o);
        lg[e] = s;
    }
    if (lane == 0) {
        float m = lg[0];
        #pragma unroll
        for (int e = 1; e < E_NUM; e++) m = fmaxf(m, lg[e]);
        float p[E_NUM], sum = 0.f;
        #pragma unroll
        for (int e = 0; e < E_NUM; e++) { p[e] = expf(lg[e] - m); sum += p[e]; }
        float inv = 1.f / sum;
        #pragma unroll
        for (int e = 0; e < E_NUM; e++) {
            p[e] *= inv;
            logits_out[(size_t)t * E_NUM + e] = lg[e];
        }
        int i0 = 0;
        #pragma unroll
        for (int e = 1; e < E_NUM; e++) if (p[e] > p[i0]) i0 = e;
        int i1 = (i0 == 0) ? 1 : 0;
        #pragma unroll
        for (int e = 0; e < E_NUM; e++) if (e != i1 && e != i0 && p[e] > p[i1]) i1 = e;
        float w0 = p[i0], w1 = p[i1];
        float s2 = w0 + w1 + 1e-20f;
        w0 = (w0 / s2) * 0.5f;
        w1 = (w1 / s2) * 0.5f;
        int p0 = atomicAdd(&g_count[i0], 1);
        g_list_tok[i0 * CAP + p0] = t;  g_list_w[i0 * CAP + p0] = w0;
        int p1 = atomicAdd(&g_count[i1], 1);
        g_list_tok[i1 * CAP + p1] = t;  g_list_w[i1 * CAP + p1] = w1;
    }
}

// ---------------- weight convert+transpose -> fp16 -------------------------------
__device__ __forceinline__ void wconv_body(const float* __restrict__ W,
                                           __half* __restrict__ wh,
                                           int K, int N) {
    __shared__ float s[32][33];
    int e = blockIdx.z;
    int k0 = blockIdx.y * 32, n0 = blockIdx.x * 32;
    const float* src = W + (size_t)e * K * N;
    int tx = threadIdx.x, ty = threadIdx.y;
    #pragma unroll
    for (int i = 0; i < 4; i++)
        s[ty + 8 * i][tx] = src[(size_t)(k0 + ty + 8 * i) * N + n0 + tx];
    __syncthreads();
    size_t ob = (size_t)e * N * K;
    #pragma unroll
    for (int i = 0; i < 4; i++) {
        int n = n0 + ty + 8 * i;
        wh[ob + (size_t)n * K + k0 + tx] = __float2half_rn(s[tx][ty + 8 * i]);
    }
}
__global__ void wconv1_kernel(const float* __restrict__ W) { wconv_body(W, g_w1t, H_DIM, I_DIM); }
__global__ void wconv2_kernel(const float* __restrict__ W) { wconv_body(W, g_w2t, I_DIM, H_DIM); }

// ---------------- GEMM core (256 threads, 8 warps, warp tile 32x64) --------------
struct LoadCtx {
    const char *aP, *bP;
    uint32_t sRow, gOff, smem0;
};

__device__ __forceinline__ void issue_stage(const LoadCtx& L, int s, int k0elem) {
    uint32_t sb = L.smem0 + s * STG_BYTES + L.sRow;
    size_t gk = (size_t)k0elem * 2 + L.gOff;
    #pragma unroll
    for (int q = 0; q < 4; q++) {
        cp16(sb + OFF_A + q * 16, L.aP + gk + q * 16);
        cp16(sb + OFF_B + q * 16, L.bP + gk + q * 16);
    }
}

__device__ __forceinline__ void compute_stage(uint32_t sb,
        const uint32_t* aOff, const uint32_t* bOff, float acc[2][8][4]) {
    #pragma unroll
    for (int ks = 0; ks < 4; ks++) {
        uint32_t a[2][4], b[4][4];
        #pragma unroll
        for (int mi = 0; mi < 2; mi++)
            ldsm4(a[mi], sb + OFF_A + aOff[mi] + ks * 32);
        #pragma unroll
        for (int nt = 0; nt < 4; nt++)
            ldsm4(b[nt], sb + OFF_B + bOff[nt] + ks * 32);
        #pragma unroll
        for (int mi = 0; mi < 2; mi++) {
            #pragma unroll
            for (int ni = 0; ni < 8; ni++) {
                int nt = ni >> 1, j = ni & 1;
                uint32_t bf[2] = { b[nt][j], b[nt][j + 2] };
                mma_f16(acc[mi][ni], a[mi], bf);
            }
        }
    }
}

// ---------------- GEMM1: h = relu(gather(x) @ W1t + b1) -> fp16 ------------------
__global__ __launch_bounds__(256, 2) void gemm1_kernel(const float* __restrict__ b1) {
    extern __shared__ char smem[];
    const int e = blockIdx.z;
    const int cnt = g_count[e];
    const int m_base = blockIdx.y * 128;
    if (m_base >= cnt) return;
    const int off = e * CAP;
    const int n_base = blockIdx.x * 128;
    const int tid = threadIdx.x;
    const int w = tid >> 5, lane = tid & 31;
    const int wm = w & 3, wn = w >> 2;           // wm: 4 (32 rows each), wn: 2 (64 cols each)

    LoadCtx L;
    {
        int rowIdx = tid >> 1;                   // 128 rows, 2 threads/row
        int gm = m_base + rowIdx;
        int tok = g_list_tok[off + ((gm < cnt) ? gm : 0)];
        L.aP = (const char*)(g_xh + (size_t)tok * H_DIM);
        size_t rB = ((size_t)e * I_DIM + (n_base + rowIdx)) * H_DIM;
        L.bP = (const char*)(g_w1t + rB);
        L.gOff = (tid & 1) * 64;
        L.sRow = (uint32_t)rowIdx * ROWB + L.gOff;
        L.smem0 = smem_to_u32(smem);
    }

    uint32_t aOff[2], bOff[4];
    {
        int mat = lane >> 3, lr = lane & 7;
        uint32_t kb = (uint32_t)(lane >> 4) * 16;
        #pragma unroll
        for (int mi = 0; mi < 2; mi++)
            aOff[mi] = (uint32_t)(wm * 32 + mi * 16 + ((mat & 1) << 3) + lr) * ROWB + kb;
        #pragma unroll
        for (int nt = 0; nt < 4; nt++)
            bOff[nt] = (uint32_t)(wn * 64 + nt * 16 + ((mat & 1) << 3) + lr) * ROWB + kb;
    }

    float acc[2][8][4] = {};

    const int NC = H_DIM / KC;   // 8
    issue_stage(L, 0, 0);   CP_COMMIT();
    issue_stage(L, 1, KC);  CP_COMMIT();
    for (int c = 0; c < NC; c++) {
        if (c + 2 < NC) CP_WAIT1(); else CP_WAIT0();
        __syncthreads();
        if (c + 2 < NC) { issue_stage(L, (c + 2) % NSTAGE, (c + 2) * KC); CP_COMMIT(); }
        compute_stage(L.smem0 + (c % NSTAGE) * STG_BYTES, aOff, bOff, acc);
    }

    int qrow = lane >> 2, qcol = (lane & 3) * 2;
    #pragma unroll
    for (int mi = 0; mi < 2; mi++) {
        #pragma unroll
        for (int half = 0; half < 2; half++) {
            int row = wm * 32 + mi * 16 + qrow + half * 8;
            int gm = m_base + row;
            if (gm >= cnt) continue;
            size_t pair = (size_t)(off + gm);
            #pragma unroll
            for (int ni = 0; ni < 8; ni++) {
                int n = n_base + wn * 64 + ni * 8 + qcol;
                float v0 = fmaxf(acc[mi][ni][half * 2 + 0] + b1[e * I_DIM + n],     0.f);
                float v1 = fmaxf(acc[mi][ni][half * 2 + 1] + b1[e * I_DIM + n + 1], 0.f);
                __half2 hp = __floats2half2_rn(v0, v1);
                *reinterpret_cast<__half2*>(g_h + pair * I_DIM + n) = hp;
            }
        }
    }
}

// ---------------- GEMM2: out[tok] += wgt * (h @ W2t + b2) ------------------------
__global__ __launch_bounds__(256, 2) void gemm2_kernel(const float* __restrict__ b2,
                                                       float* __restrict__ out) {
    extern __shared__ char smem[];
    const int e = blockIdx.z;
    const int cnt = g_count[e];
    const int m_base = blockIdx.y * 128;
    if (m_base >= cnt) return;
    const int off = e * CAP;
    const int n_base = blockIdx.x * 128;
    const int tid = threadIdx.x;
    const int w = tid >> 5, lane = tid & 31;
    const int wm = w & 3, wn = w >> 2;

    LoadCtx L;
    {
        int rowIdx = tid >> 1;
        int gm = m_base + rowIdx;
        size_t pr = (size_t)(off + ((gm < cnt) ? gm : 0));
        L.aP = (const char*)(g_h + pr * I_DIM);
        size_t rB = ((size_t)e * H_DIM + (n_base + rowIdx)) * I_DIM;
        L.bP = (const char*)(g_w2t + rB);
        L.gOff = (tid & 1) * 64;
        L.sRow = (uint32_t)rowIdx * ROWB + L.gOff;
        L.smem0 = smem_to_u32(smem);
    }

    uint32_t aOff[2], bOff[4];
    {
        int mat = lane >> 3, lr = lane & 7;
        uint32_t kb = (uint32_t)(lane >> 4) * 16;
        #pragma unroll
        for (int mi = 0; mi < 2; mi++)
            aOff[mi] = (uint32_t)(wm * 32 + mi * 16 + ((mat & 1) << 3) + lr) * ROWB + kb;
        #pragma unroll
        for (int nt = 0; nt < 4; nt++)
            bOff[nt] = (uint32_t)(wn * 64 + nt * 16 + ((mat & 1) << 3) + lr) * ROWB + kb;
    }

    float acc[2][8][4] = {};

    const int NC = I_DIM / KC;   // 16
    issue_stage(L, 0, 0);   CP_COMMIT();
    issue_stage(L, 1, KC);  CP_COMMIT();
    for (int c = 0; c < NC; c++) {
        if (c + 2 < NC) CP_WAIT1(); else CP_WAIT0();
        __syncthreads();
        if (c + 2 < NC) { issue_stage(L, (c + 2) % NSTAGE, (c + 2) * KC); CP_COMMIT(); }
        compute_stage(L.smem0 + (c % NSTAGE) * STG_BYTES, aOff, bOff, acc);
    }

    int qrow = lane >> 2, qcol = (lane & 3) * 2;
    #pragma unroll
    for (int mi = 0; mi < 2; mi++) {
        #pragma unroll
        for (int half = 0; half < 2; half++) {
            int row = wm * 32 + mi * 16 + qrow + half * 8;
            int gm = m_base + row;
            if (gm >= cnt) continue;
            int tok = g_list_tok[off + gm];
            float wgt = g_list_w[off + gm];
            float* dst = out + (size_t)tok * H_DIM;
            #pragma unroll
            for (int ni = 0; ni < 8; ni++) {
                int n = n_base + wn * 64 + ni * 8 + qcol;
                atomicAdd(&dst[n],     wgt * (acc[mi][ni][half * 2 + 0] + b2[e * H_DIM + n]));
                atomicAdd(&dst[n + 1], wgt * (acc[mi][ni][half * 2 + 1] + b2[e * H_DIM + n + 1]));
            }
        }
    }
}

// ---------------- launch ----------------------------------------------------------
extern "C" void kernel_launch(void* const* d_in, const int* in_sizes, int n_in,
                              void* d_out, int out_size) {
    const float* x  = (const float*)d_in[0];
    const float* gw = (const float*)d_in[1];
    const float* w1 = (const float*)d_in[2];
    const float* b1 = (const float*)d_in[3];
    const float* w2 = (const float*)d_in[4];
    const float* b2 = (const float*)d_in[5];
    float* out = (float*)d_out;
    float* logits = out + (size_t)T_TOKENS * H_DIM;

    cudaFuncSetAttribute(gemm1_kernel, cudaFuncAttributeMaxDynamicSharedMemorySize, SMEM_BYTES);
    cudaFuncSetAttribute(gemm2_kernel, cudaFuncAttributeMaxDynamicSharedMemorySize, SMEM_BYTES);

    zero_small_kernel<<<1, 32>>>();
    router_kernel<<<T_TOKENS / 8, 256>>>(x, gw, logits, (float4*)out);

    wconv1_kernel<<<dim3(I_DIM / 32, H_DIM / 32, E_NUM), dim3(32, 8)>>>(w1);
    wconv2_kernel<<<dim3(H_DIM / 32, I_DIM / 32, E_NUM), dim3(32, 8)>>>(w2);

    dim3 g1(I_DIM / 128, T_TOKENS / 128, E_NUM);
    gemm1_kernel<<<g1, 256, SMEM_BYTES>>>(b1);

    dim3 g2(H_DIM / 128, T_TOKENS / 128, E_NUM);
    gemm2_kernel<<<g2, 256, SMEM_BYTES>>>(b2, out);
}

// round 11
// speedup vs baseline: 1.0802x; 1.0802x over previous
#include <cuda_runtime.h>
#include <cuda_fp16.h>
#include <cstdint>
#include <math.h>

#define T_TOKENS 8192
#define H_DIM    512
#define I_DIM    1024
#define E_NUM    8
#define CAP      T_TOKENS                // per-expert capacity
#define KC       64                      // K elems per stage (128B rows)

// ---------------- smem layout -------------------------------------------------
// per stage: 2 tiles (A, B), each 128 rows x 64 fp16, row stride 144B.
#define ROWB      144
#define TILE_SZ   (128 * ROWB)           // 18432 B
#define OFF_A     0
#define OFF_B     TILE_SZ
#define STG_BYTES (2 * TILE_SZ)          // 36864 B
#define NSTAGE    3
#define SMEM_BYTES (NSTAGE * STG_BYTES)  // 110592 B

// ---------------- PTX helpers ---------------------------------------------------
__device__ __forceinline__ uint32_t smem_to_u32(const void* p) {
    uint32_t a;
    asm("{ .reg .u64 t; cvta.to.shared.u64 t, %1; cvt.u32.u64 %0, t; }" : "=r"(a) : "l"(p));
    return a;
}
__device__ __forceinline__ void cp16(uint32_t s, const void* g) {
    asm volatile("cp.async.cg.shared.global [%0], [%1], 16;" :: "r"(s), "l"(g));
}
#define CP_COMMIT() asm volatile("cp.async.commit_group;" ::: "memory")
#define CP_WAIT1()  asm volatile("cp.async.wait_group 1;" ::: "memory")
#define CP_WAIT0()  asm volatile("cp.async.wait_group 0;" ::: "memory")

__device__ __forceinline__ void ldsm4(uint32_t* r, uint32_t a) {
    asm volatile("ldmatrix.sync.aligned.m8n8.x4.shared.b16 {%0,%1,%2,%3}, [%4];"
        : "=r"(r[0]), "=r"(r[1]), "=r"(r[2]), "=r"(r[3]) : "r"(a));
}
__device__ __forceinline__ void mma_f16(float* c, const uint32_t* a, const uint32_t* b) {
    asm volatile("mma.sync.aligned.m16n8k16.row.col.f32.f16.f16.f32 "
        "{%0,%1,%2,%3}, {%4,%5,%6,%7}, {%8,%9}, {%0,%1,%2,%3};"
        : "+f"(c[0]), "+f"(c[1]), "+f"(c[2]), "+f"(c[3])
        : "r"(a[0]), "r"(a[1]), "r"(a[2]), "r"(a[3]), "r"(b[0]), "r"(b[1]));
}

// ---------------- scratch (device globals) -------------------------------------
__device__ int   g_count[E_NUM];
__device__ int   g_list_tok[E_NUM * CAP];
__device__ float g_list_w[E_NUM * CAP];

__device__ __half g_xh[(size_t)T_TOKENS * H_DIM];
__device__ __half g_w1t[(size_t)E_NUM * I_DIM * H_DIM];   // [e][n=I][k=H]
__device__ __half g_w2t[(size_t)E_NUM * H_DIM * I_DIM];   // [e][n=H][k=I]
__device__ __half g_h[(size_t)E_NUM * CAP * I_DIM];

// ------- router (fused: logits, top-2, x->fp16, direct scatter) -----------------
__global__ void router_kernel(const float* __restrict__ x,
                              const float* __restrict__ gw,
                              float* __restrict__ logits_out) {
    int tid = threadIdx.x;
    int warp = tid >> 5, lane = tid & 31;
    int t = blockIdx.x * 8 + warp;

    float xr[16];
    #pragma unroll
    for (int j = 0; j < 16; j++) xr[j] = x[(size_t)t * H_DIM + lane + 32 * j];

    #pragma unroll
    for (int j = 0; j < 16; j++)
        g_xh[(size_t)t * H_DIM + lane + 32 * j] = __float2half_rn(xr[j]);

    float lg[E_NUM];
    #pragma unroll
    for (int e = 0; e < E_NUM; e++) {
        float s = 0.f;
        const float* g = gw + (size_t)e * H_DIM + lane;
        #pragma unroll
        for (int j = 0; j < 16; j++) s = fmaf(xr[j], g[32 * j], s);
        #pragma unroll
        for (int o = 16; o; o >>= 1) s += __shfl_xor_sync(0xffffffffu, s, o);
        lg[e] = s;
    }
    if (lane == 0) {
        float m = lg[0];
        #pragma unroll
        for (int e = 1; e < E_NUM; e++) m = fmaxf(m, lg[e]);
        float p[E_NUM], sum = 0.f;
        #pragma unroll
        for (int e = 0; e < E_NUM; e++) { p[e] = expf(lg[e] - m); sum += p[e]; }
        float inv = 1.f / sum;
        #pragma unroll
        for (int e = 0; e < E_NUM; e++) {
            p[e] *= inv;
            logits_out[(size_t)t * E_NUM + e] = lg[e];
        }
        int i0 = 0;
        #pragma unroll
        for (int e = 1; e < E_NUM; e++) if (p[e] > p[i0]) i0 = e;
        int i1 = (i0 == 0) ? 1 : 0;
        #pragma unroll
        for (int e = 0; e < E_NUM; e++) if (e != i1 && e != i0 && p[e] > p[i1]) i1 = e;
        float w0 = p[i0], w1 = p[i1];
        float s2 = w0 + w1 + 1e-20f;
        w0 = (w0 / s2) * 0.5f;
        w1 = (w1 / s2) * 0.5f;
        int p0 = atomicAdd(&g_count[i0], 1);
        g_list_tok[i0 * CAP + p0] = t;  g_list_w[i0 * CAP + p0] = w0;
        int p1 = atomicAdd(&g_count[i1], 1);
        g_list_tok[i1 * CAP + p1] = t;  g_list_w[i1 * CAP + p1] = w1;
    }
}

// ---------------- weight convert+transpose -> fp16 -------------------------------
__device__ __forceinline__ void wconv_body(const float* __restrict__ W,
                                           __half* __restrict__ wh,
                                           int K, int N) {
    __shared__ float s[32][33];
    int e = blockIdx.z;
    int k0 = blockIdx.y * 32, n0 = blockIdx.x * 32;
    const float* src = W + (size_t)e * K * N;
    int tx = threadIdx.x, ty = threadIdx.y;
    #pragma unroll
    for (int i = 0; i < 4; i++)
        s[ty + 8 * i][tx] = src[(size_t)(k0 + ty + 8 * i) * N + n0 + tx];
    __syncthreads();
    size_t ob = (size_t)e * N * K;
    #pragma unroll
    for (int i = 0; i < 4; i++) {
        int n = n0 + ty + 8 * i;
        wh[ob + (size_t)n * K + k0 + tx] = __float2half_rn(s[tx][ty + 8 * i]);
    }
}
__global__ void wconv1_kernel(const float* __restrict__ W) { wconv_body(W, g_w1t, H_DIM, I_DIM); }
__global__ void wconv2_kernel(const float* __restrict__ W) { wconv_body(W, g_w2t, I_DIM, H_DIM); }

// ---------------- GEMM core ------------------------------------------------------
struct LoadCtx {
    const char *aP, *bP;
    uint32_t sRow, gOff, smem0;
};

__device__ __forceinline__ void issue_stage(const LoadCtx& L, int s, int k0elem) {
    uint32_t sb = L.smem0 + s * STG_BYTES + L.sRow;
    size_t gk = (size_t)k0elem * 2 + L.gOff;
    cp16(sb + OFF_A,      L.aP + gk);
    cp16(sb + OFF_A + 16, L.aP + gk + 16);
    cp16(sb + OFF_B,      L.bP + gk);
    cp16(sb + OFF_B + 16, L.bP + gk + 16);
}

__device__ __forceinline__ void compute_stage(uint32_t sb,
        const uint32_t* aOff, const uint32_t* bOff, float acc[2][4][4]) {
    #pragma unroll
    for (int ks = 0; ks < 4; ks++) {
        uint32_t a[2][4], b[2][4];
        #pragma unroll
        for (int mi = 0; mi < 2; mi++)
            ldsm4(a[mi], sb + OFF_A + aOff[mi] + ks * 32);
        #pragma unroll
        for (int nt = 0; nt < 2; nt++)
            ldsm4(b[nt], sb + OFF_B + bOff[nt] + ks * 32);
        #pragma unroll
        for (int mi = 0; mi < 2; mi++) {
            #pragma unroll
            for (int ni = 0; ni < 4; ni++) {
                int nt = ni >> 1, j = ni & 1;
                uint32_t bf[2] = { b[nt][j], b[nt][j + 2] };
                mma_f16(acc[mi][ni], a[mi], bf);
            }
        }
    }
}

// ---------------- GEMM1: h = relu(gather(x) @ W1t + b1) -> fp16 ------------------
__global__ __launch_bounds__(512, 1) void gemm1_kernel(const float* __restrict__ b1) {
    extern __shared__ char smem[];
    const int e = blockIdx.z;
    const int cnt = g_count[e];
    const int m_base = blockIdx.y * 128;
    if (m_base >= cnt) return;
    const int off = e * CAP;
    const int n_base = blockIdx.x * 128;
    const int tid = threadIdx.x;
    const int w = tid >> 5, lane = tid & 31;
    const int wm = w & 3, wn = w >> 2;

    LoadCtx L;
    {
        int rowIdx = tid >> 2;
        int gm = m_base + rowIdx;
        int tok = g_list_tok[off + ((gm < cnt) ? gm : 0)];
        L.aP = (const char*)(g_xh + (size_t)tok * H_DIM);
        size_t rB = ((size_t)e * I_DIM + (n_base + rowIdx)) * H_DIM;
        L.bP = (const char*)(g_w1t + rB);
        L.gOff = (tid & 3) * 32;
        L.sRow = (uint32_t)rowIdx * ROWB + L.gOff;
        L.smem0 = smem_to_u32(smem);
    }

    uint32_t aOff[2], bOff[2];
    {
        int mat = lane >> 3, lr = lane & 7;
        uint32_t kb = (uint32_t)(lane >> 4) * 16;
        #pragma unroll
        for (int mi = 0; mi < 2; mi++)
            aOff[mi] = (uint32_t)(wm * 32 + mi * 16 + ((mat & 1) << 3) + lr) * ROWB + kb;
        #pragma unroll
        for (int nt = 0; nt < 2; nt++)
            bOff[nt] = (uint32_t)(wn * 32 + nt * 16 + ((mat & 1) << 3) + lr) * ROWB + kb;
    }

    float acc[2][4][4] = {};

    const int NC = H_DIM / KC;   // 8
    issue_stage(L, 0, 0);   CP_COMMIT();
    issue_stage(L, 1, KC);  CP_COMMIT();
    for (int c = 0; c < NC; c++) {
        if (c + 2 < NC) CP_WAIT1(); else CP_WAIT0();
        __syncthreads();
        if (c + 2 < NC) { issue_stage(L, (c + 2) % NSTAGE, (c + 2) * KC); CP_COMMIT(); }
        compute_stage(L.smem0 + (c % NSTAGE) * STG_BYTES, aOff, bOff, acc);
    }

    int qrow = lane >> 2, qcol = (lane & 3) * 2;
    #pragma unroll
    for (int mi = 0; mi < 2; mi++) {
        #pragma unroll
        for (int half = 0; half < 2; half++) {
            int row = wm * 32 + mi * 16 + qrow + half * 8;
            int gm = m_base + row;
            if (gm >= cnt) continue;
            size_t pair = (size_t)(off + gm);
            #pragma unroll
            for (int ni = 0; ni < 4; ni++) {
                int n = n_base + wn * 32 + ni * 8 + qcol;
                float v0 = fmaxf(acc[mi][ni][half * 2 + 0] + b1[e * I_DIM + n],     0.f);
                float v1 = fmaxf(acc[mi][ni][half * 2 + 1] + b1[e * I_DIM + n + 1], 0.f);
                __half2 hp = __floats2half2_rn(v0, v1);
                *reinterpret_cast<__half2*>(g_h + pair * I_DIM + n) = hp;
            }
        }
    }
}

// ---------------- GEMM2: out[tok] += wgt * (h @ W2t + b2) ------------------------
__global__ __launch_bounds__(512, 1) void gemm2_kernel(const float* __restrict__ b2,
                                                       float* __restrict__ out) {
    extern __shared__ char smem[];
    const int e = blockIdx.z;
    const int cnt = g_count[e];
    const int m_base = blockIdx.y * 128;
    if (m_base >= cnt) return;
    const int off = e * CAP;
    const int n_base = blockIdx.x * 128;
    const int tid = threadIdx.x;
    const int w = tid >> 5, lane = tid & 31;
    const int wm = w & 3, wn = w >> 2;

    LoadCtx L;
    {
        int rowIdx = tid >> 2;
        int gm = m_base + rowIdx;
        size_t pr = (size_t)(off + ((gm < cnt) ? gm : 0));
        L.aP = (const char*)(g_h + pr * I_DIM);
        size_t rB = ((size_t)e * H_DIM + (n_base + rowIdx)) * I_DIM;
        L.bP = (const char*)(g_w2t + rB);
        L.gOff = (tid & 3) * 32;
        L.sRow = (uint32_t)rowIdx * ROWB + L.gOff;
        L.smem0 = smem_to_u32(smem);
    }

    uint32_t aOff[2], bOff[2];
    {
        int mat = lane >> 3, lr = lane & 7;
        uint32_t kb = (uint32_t)(lane >> 4) * 16;
        #pragma unroll
        for (int mi = 0; mi < 2; mi++)
            aOff[mi] = (uint32_t)(wm * 32 + mi * 16 + ((mat & 1) << 3) + lr) * ROWB + kb;
        #pragma unroll
        for (int nt = 0; nt < 2; nt++)
            bOff[nt] = (uint32_t)(wn * 32 + nt * 16 + ((mat & 1) << 3) + lr) * ROWB + kb;
    }

    float acc[2][4][4] = {};

    const int NC = I_DIM / KC;   // 16
    issue_stage(L, 0, 0);   CP_COMMIT();
    issue_stage(L, 1, KC);  CP_COMMIT();
    for (int c = 0; c < NC; c++) {
        if (c + 2 < NC) CP_WAIT1(); else CP_WAIT0();
        __syncthreads();
        if (c + 2 < NC) { issue_stage(L, (c + 2) % NSTAGE, (c + 2) * KC); CP_COMMIT(); }
        compute_stage(L.smem0 + (c % NSTAGE) * STG_BYTES, aOff, bOff, acc);
    }

    int qrow = lane >> 2, qcol = (lane & 3) * 2;
    #pragma unroll
    for (int mi = 0; mi < 2; mi++) {
        #pragma unroll
        for (int half = 0; half < 2; half++) {
            int row = wm * 32 + mi * 16 + qrow + half * 8;
            int gm = m_base + row;
            if (gm >= cnt) continue;
            int tok = g_list_tok[off + gm];
            float wgt = g_list_w[off + gm];
            float* dst = out + (size_t)tok * H_DIM;
            #pragma unroll
            for (int ni = 0; ni < 4; ni++) {
                int n = n_base + wn * 32 + ni * 8 + qcol;
                atomicAdd(&dst[n],     wgt * (acc[mi][ni][half * 2 + 0] + b2[e * H_DIM + n]));
                atomicAdd(&dst[n + 1], wgt * (acc[mi][ni][half * 2 + 1] + b2[e * H_DIM + n + 1]));
            }
        }
    }
}

// ---------------- launch ----------------------------------------------------------
extern "C" void kernel_launch(void* const* d_in, const int* in_sizes, int n_in,
                              void* d_out, int out_size) {
    const float* x  = (const float*)d_in[0];
    const float* gw = (const float*)d_in[1];
    const float* w1 = (const float*)d_in[2];
    const float* b1 = (const float*)d_in[3];
    const float* w2 = (const float*)d_in[4];
    const float* b2 = (const float*)d_in[5];
    float* out = (float*)d_out;
    float* logits = out + (size_t)T_TOKENS * H_DIM;

    cudaFuncSetAttribute(gemm1_kernel, cudaFuncAttributeMaxDynamicSharedMemorySize, SMEM_BYTES);
    cudaFuncSetAttribute(gemm2_kernel, cudaFuncAttributeMaxDynamicSharedMemorySize, SMEM_BYTES);

    // zero routed-out head + expert counters via memset nodes (full-HBM-rate, ~2us)
    cudaMemsetAsync(out, 0, (size_t)T_TOKENS * H_DIM * sizeof(float), 0);
    void* cnt_ptr = nullptr;
    cudaGetSymbolAddress(&cnt_ptr, g_count);
    cudaMemsetAsync(cnt_ptr, 0, E_NUM * sizeof(int), 0);

    router_kernel<<<T_TOKENS / 8, 256>>>(x, gw, logits);

    wconv1_kernel<<<dim3(I_DIM / 32, H_DIM / 32, E_NUM), dim3(32, 8)>>>(w1);
    wconv2_kernel<<<dim3(H_DIM / 32, I_DIM / 32, E_NUM), dim3(32, 8)>>>(w2);

    dim3 g1(I_DIM / 128, T_TOKENS / 128, E_NUM);
    gemm1_kernel<<<g1, 512, SMEM_BYTES>>>(b1);

    dim3 g2(H_DIM / 128, T_TOKENS / 128, E_NUM);
    gemm2_kernel<<<g2, 512, SMEM_BYTES>>>(b2, out);
}

// round 12
// speedup vs baseline: 1.1338x; 1.0497x over previous
#include <cuda_runtime.h>
#include <cuda_fp16.h>
#include <cstdint>
#include <math.h>

#define T_TOKENS 8192
#define H_DIM    512
#define I_DIM    1024
#define E_NUM    8
#define CAP      T_TOKENS                // per-expert capacity
#define KC       64                      // K elems per stage (128B rows)

// ---------------- smem layout -------------------------------------------------
// per stage: 2 tiles (A, B), each 128 rows x 64 fp16, row stride 144B.
#define ROWB      144
#define TILE_SZ   (128 * ROWB)           // 18432 B
#define OFF_A     0
#define OFF_B     TILE_SZ
#define STG_BYTES (2 * TILE_SZ)          // 36864 B
#define NSTAGE    2
#define SMEM_BYTES (NSTAGE * STG_BYTES)  // 73728 B -> 2 CTAs/SM (147KB < 228KB)

// ---------------- PTX helpers ---------------------------------------------------
__device__ __forceinline__ uint32_t smem_to_u32(const void* p) {
    uint32_t a;
    asm("{ .reg .u64 t; cvta.to.shared.u64 t, %1; cvt.u32.u64 %0, t; }" : "=r"(a) : "l"(p));
    return a;
}
__device__ __forceinline__ void cp16(uint32_t s, const void* g) {
    asm volatile("cp.async.cg.shared.global [%0], [%1], 16;" :: "r"(s), "l"(g));
}
#define CP_COMMIT() asm volatile("cp.async.commit_group;" ::: "memory")
#define CP_WAIT1()  asm volatile("cp.async.wait_group 1;" ::: "memory")
#define CP_WAIT0()  asm volatile("cp.async.wait_group 0;" ::: "memory")

__device__ __forceinline__ void ldsm4(uint32_t* r, uint32_t a) {
    asm volatile("ldmatrix.sync.aligned.m8n8.x4.shared.b16 {%0,%1,%2,%3}, [%4];"
        : "=r"(r[0]), "=r"(r[1]), "=r"(r[2]), "=r"(r[3]) : "r"(a));
}
__device__ __forceinline__ void mma_f16(float* c, const uint32_t* a, const uint32_t* b) {
    asm volatile("mma.sync.aligned.m16n8k16.row.col.f32.f16.f16.f32 "
        "{%0,%1,%2,%3}, {%4,%5,%6,%7}, {%8,%9}, {%0,%1,%2,%3};"
        : "+f"(c[0]), "+f"(c[1]), "+f"(c[2]), "+f"(c[3])
        : "r"(a[0]), "r"(a[1]), "r"(a[2]), "r"(a[3]), "r"(b[0]), "r"(b[1]));
}

// ---------------- scratch (device globals) -------------------------------------
__device__ int   g_count[E_NUM];
__device__ int   g_list_tok[E_NUM * CAP];
__device__ float g_list_w[E_NUM * CAP];

__device__ __half g_xh[(size_t)T_TOKENS * H_DIM];
__device__ __half g_w1t[(size_t)E_NUM * I_DIM * H_DIM];   // [e][n=I][k=H]
__device__ __half g_w2t[(size_t)E_NUM * H_DIM * I_DIM];   // [e][n=H][k=I]
__device__ __half g_h[(size_t)E_NUM * CAP * I_DIM];

// ------- router (fused: logits, top-2, x->fp16, direct scatter) -----------------
__global__ void router_kernel(const float* __restrict__ x,
                              const float* __restrict__ gw,
                              float* __restrict__ logits_out) {
    int tid = threadIdx.x;
    int warp = tid >> 5, lane = tid & 31;
    int t = blockIdx.x * 8 + warp;

    float xr[16];
    #pragma unroll
    for (int j = 0; j < 16; j++) xr[j] = x[(size_t)t * H_DIM + lane + 32 * j];

    #pragma unroll
    for (int j = 0; j < 16; j++)
        g_xh[(size_t)t * H_DIM + lane + 32 * j] = __float2half_rn(xr[j]);

    float lg[E_NUM];
    #pragma unroll
    for (int e = 0; e < E_NUM; e++) {
        float s = 0.f;
        const float* g = gw + (size_t)e * H_DIM + lane;
        #pragma unroll
        for (int j = 0; j < 16; j++) s = fmaf(xr[j], g[32 * j], s);
        #pragma unroll
        for (int o = 16; o; o >>= 1) s += __shfl_xor_sync(0xffffffffu, s, o);
        lg[e] = s;
    }
    if (lane == 0) {
        float m = lg[0];
        #pragma unroll
        for (int e = 1; e < E_NUM; e++) m = fmaxf(m, lg[e]);
        float p[E_NUM], sum = 0.f;
        #pragma unroll
        for (int e = 0; e < E_NUM; e++) { p[e] = expf(lg[e] - m); sum += p[e]; }
        float inv = 1.f / sum;
        #pragma unroll
        for (int e = 0; e < E_NUM; e++) {
            p[e] *= inv;
            logits_out[(size_t)t * E_NUM + e] = lg[e];
        }
        int i0 = 0;
        #pragma unroll
        for (int e = 1; e < E_NUM; e++) if (p[e] > p[i0]) i0 = e;
        int i1 = (i0 == 0) ? 1 : 0;
        #pragma unroll
        for (int e = 0; e < E_NUM; e++) if (e != i1 && e != i0 && p[e] > p[i1]) i1 = e;
        float w0 = p[i0], w1 = p[i1];
        float s2 = w0 + w1 + 1e-20f;
        w0 = (w0 / s2) * 0.5f;
        w1 = (w1 / s2) * 0.5f;
        int p0 = atomicAdd(&g_count[i0], 1);
        g_list_tok[i0 * CAP + p0] = t;  g_list_w[i0 * CAP + p0] = w0;
        int p1 = atomicAdd(&g_count[i1], 1);
        g_list_tok[i1 * CAP + p1] = t;  g_list_w[i1 * CAP + p1] = w1;
    }
}

// ---------------- weight convert+transpose -> fp16 -------------------------------
__device__ __forceinline__ void wconv_body(const float* __restrict__ W,
                                           __half* __restrict__ wh,
                                           int K, int N) {
    __shared__ float s[32][33];
    int e = blockIdx.z;
    int k0 = blockIdx.y * 32, n0 = blockIdx.x * 32;
    const float* src = W + (size_t)e * K * N;
    int tx = threadIdx.x, ty = threadIdx.y;
    #pragma unroll
    for (int i = 0; i < 4; i++)
        s[ty + 8 * i][tx] = src[(size_t)(k0 + ty + 8 * i) * N + n0 + tx];
    __syncthreads();
    size_t ob = (size_t)e * N * K;
    #pragma unroll
    for (int i = 0; i < 4; i++) {
        int n = n0 + ty + 8 * i;
        wh[ob + (size_t)n * K + k0 + tx] = __float2half_rn(s[tx][ty + 8 * i]);
    }
}
__global__ void wconv1_kernel(const float* __restrict__ W) { wconv_body(W, g_w1t, H_DIM, I_DIM); }
__global__ void wconv2_kernel(const float* __restrict__ W) { wconv_body(W, g_w2t, I_DIM, H_DIM); }

// ---------------- GEMM core ------------------------------------------------------
struct LoadCtx {
    const char *aP, *bP;
    uint32_t sRow, gOff, smem0;
};

__device__ __forceinline__ void issue_stage(const LoadCtx& L, int s, int k0elem) {
    uint32_t sb = L.smem0 + s * STG_BYTES + L.sRow;
    size_t gk = (size_t)k0elem * 2 + L.gOff;
    cp16(sb + OFF_A,      L.aP + gk);
    cp16(sb + OFF_A + 16, L.aP + gk + 16);
    cp16(sb + OFF_B,      L.bP + gk);
    cp16(sb + OFF_B + 16, L.bP + gk + 16);
}

__device__ __forceinline__ void compute_stage(uint32_t sb,
        const uint32_t* aOff, const uint32_t* bOff, float acc[2][4][4]) {
    #pragma unroll
    for (int ks = 0; ks < 4; ks++) {
        uint32_t a[2][4], b[2][4];
        #pragma unroll
        for (int mi = 0; mi < 2; mi++)
            ldsm4(a[mi], sb + OFF_A + aOff[mi] + ks * 32);
        #pragma unroll
        for (int nt = 0; nt < 2; nt++)
            ldsm4(b[nt], sb + OFF_B + bOff[nt] + ks * 32);
        #pragma unroll
        for (int mi = 0; mi < 2; mi++) {
            #pragma unroll
            for (int ni = 0; ni < 4; ni++) {
                int nt = ni >> 1, j = ni & 1;
                uint32_t bf[2] = { b[nt][j], b[nt][j + 2] };
                mma_f16(acc[mi][ni], a[mi], bf);
            }
        }
    }
}

// ---------------- GEMM1: h = relu(gather(x) @ W1t + b1) -> fp16 ------------------
__global__ __launch_bounds__(512, 2) void gemm1_kernel(const float* __restrict__ b1) {
    extern __shared__ char smem[];
    const int e = blockIdx.z;
    const int cnt = g_count[e];
    const int m_base = blockIdx.y * 128;
    if (m_base >= cnt) return;
    const int off = e * CAP;
    const int n_base = blockIdx.x * 128;
    const int tid = threadIdx.x;
    const int w = tid >> 5, lane = tid & 31;
    const int wm = w & 3, wn = w >> 2;

    LoadCtx L;
    {
        int rowIdx = tid >> 2;
        int gm = m_base + rowIdx;
        int tok = g_list_tok[off + ((gm < cnt) ? gm : 0)];
        L.aP = (const char*)(g_xh + (size_t)tok * H_DIM);
        size_t rB = ((size_t)e * I_DIM + (n_base + rowIdx)) * H_DIM;
        L.bP = (const char*)(g_w1t + rB);
        L.gOff = (tid & 3) * 32;
        L.sRow = (uint32_t)rowIdx * ROWB + L.gOff;
        L.smem0 = smem_to_u32(smem);
    }

    uint32_t aOff[2], bOff[2];
    {
        int mat = lane >> 3, lr = lane & 7;
        uint32_t kb = (uint32_t)(lane >> 4) * 16;
        #pragma unroll
        for (int mi = 0; mi < 2; mi++)
            aOff[mi] = (uint32_t)(wm * 32 + mi * 16 + ((mat & 1) << 3) + lr) * ROWB + kb;
        #pragma unroll
        for (int nt = 0; nt < 2; nt++)
            bOff[nt] = (uint32_t)(wn * 32 + nt * 16 + ((mat & 1) << 3) + lr) * ROWB + kb;
    }

    float acc[2][4][4] = {};

    const int NC = H_DIM / KC;   // 8
    issue_stage(L, 0, 0);   CP_COMMIT();
    for (int c = 0; c < NC; c++) {
        if (c + 1 < NC) { issue_stage(L, (c + 1) & 1, (c + 1) * KC); CP_COMMIT(); CP_WAIT1(); }
        else CP_WAIT0();
        __syncthreads();
        compute_stage(L.smem0 + (c & 1) * STG_BYTES, aOff, bOff, acc);
        __syncthreads();
    }

    int qrow = lane >> 2, qcol = (lane & 3) * 2;
    #pragma unroll
    for (int mi = 0; mi < 2; mi++) {
        #pragma unroll
        for (int half = 0; half < 2; half++) {
            int row = wm * 32 + mi * 16 + qrow + half * 8;
            int gm = m_base + row;
            if (gm >= cnt) continue;
            size_t pair = (size_t)(off + gm);
            #pragma unroll
            for (int ni = 0; ni < 4; ni++) {
                int n = n_base + wn * 32 + ni * 8 + qcol;
                float v0 = fmaxf(acc[mi][ni][half * 2 + 0] + b1[e * I_DIM + n],     0.f);
                float v1 = fmaxf(acc[mi][ni][half * 2 + 1] + b1[e * I_DIM + n + 1], 0.f);
                __half2 hp = __floats2half2_rn(v0, v1);
                *reinterpret_cast<__half2*>(g_h + pair * I_DIM + n) = hp;
            }
        }
    }
}

// ---------------- GEMM2: out[tok] += wgt * (h @ W2t + b2) ------------------------
__global__ __launch_bounds__(512, 2) void gemm2_kernel(const float* __restrict__ b2,
                                                       float* __restrict__ out) {
    extern __shared__ char smem[];
    const int e = blockIdx.z;
    const int cnt = g_count[e];
    const int m_base = blockIdx.y * 128;
    if (m_base >= cnt) return;
    const int off = e * CAP;
    const int n_base = blockIdx.x * 128;
    const int tid = threadIdx.x;
    const int w = tid >> 5, lane = tid & 31;
    const int wm = w & 3, wn = w >> 2;

    LoadCtx L;
    {
        int rowIdx = tid >> 2;
        int gm = m_base + rowIdx;
        size_t pr = (size_t)(off + ((gm < cnt) ? gm : 0));
        L.aP = (const char*)(g_h + pr * I_DIM);
        size_t rB = ((size_t)e * H_DIM + (n_base + rowIdx)) * I_DIM;
        L.bP = (const char*)(g_w2t + rB);
        L.gOff = (tid & 3) * 32;
        L.sRow = (uint32_t)rowIdx * ROWB + L.gOff;
        L.smem0 = smem_to_u32(smem);
    }

    uint32_t aOff[2], bOff[2];
    {
        int mat = lane >> 3, lr = lane & 7;
        uint32_t kb = (uint32_t)(lane >> 4) * 16;
        #pragma unroll
        for (int mi = 0; mi < 2; mi++)
            aOff[mi] = (uint32_t)(wm * 32 + mi * 16 + ((mat & 1) << 3) + lr) * ROWB + kb;
        #pragma unroll
        for (int nt = 0; nt < 2; nt++)
            bOff[nt] = (uint32_t)(wn * 32 + nt * 16 + ((mat & 1) << 3) + lr) * ROWB + kb;
    }

    float acc[2][4][4] = {};

    const int NC = I_DIM / KC;   // 16
    issue_stage(L, 0, 0);   CP_COMMIT();
    for (int c = 0; c < NC; c++) {
        if (c + 1 < NC) { issue_stage(L, (c + 1) & 1, (c + 1) * KC); CP_COMMIT(); CP_WAIT1(); }
        else CP_WAIT0();
        __syncthreads();
        compute_stage(L.smem0 + (c & 1) * STG_BYTES, aOff, bOff, acc);
        __syncthreads();
    }

    int qrow = lane >> 2, qcol = (lane & 3) * 2;
    #pragma unroll
    for (int mi = 0; mi < 2; mi++) {
        #pragma unroll
        for (int half = 0; half < 2; half++) {
            int row = wm * 32 + mi * 16 + qrow + half * 8;
            int gm = m_base + row;
            if (gm >= cnt) continue;
            int tok = g_list_tok[off + gm];
            float wgt = g_list_w[off + gm];
            float* dst = out + (size_t)tok * H_DIM;
            #pragma unroll
            for (int ni = 0; ni < 4; ni++) {
                int n = n_base + wn * 32 + ni * 8 + qcol;
                atomicAdd(&dst[n],     wgt * (acc[mi][ni][half * 2 + 0] + b2[e * H_DIM + n]));
                atomicAdd(&dst[n + 1], wgt * (acc[mi][ni][half * 2 + 1] + b2[e * H_DIM + n + 1]));
            }
        }
    }
}

// ---------------- launch ----------------------------------------------------------
extern "C" void kernel_launch(void* const* d_in, const int* in_sizes, int n_in,
                              void* d_out, int out_size) {
    const float* x  = (const float*)d_in[0];
    const float* gw = (const float*)d_in[1];
    const float* w1 = (const float*)d_in[2];
    const float* b1 = (const float*)d_in[3];
    const float* w2 = (const float*)d_in[4];
    const float* b2 = (const float*)d_in[5];
    float* out = (float*)d_out;
    float* logits = out + (size_t)T_TOKENS * H_DIM;

    cudaFuncSetAttribute(gemm1_kernel, cudaFuncAttributeMaxDynamicSharedMemorySize, SMEM_BYTES);
    cudaFuncSetAttribute(gemm2_kernel, cudaFuncAttributeMaxDynamicSharedMemorySize, SMEM_BYTES);

    cudaMemsetAsync(out, 0, (size_t)T_TOKENS * H_DIM * sizeof(float), 0);
    void* cnt_ptr = nullptr;
    cudaGetSymbolAddress(&cnt_ptr, g_count);
    cudaMemsetAsync(cnt_ptr, 0, E_NUM * sizeof(int), 0);

    router_kernel<<<T_TOKENS / 8, 256>>>(x, gw, logits);

    wconv1_kernel<<<dim3(I_DIM / 32, H_DIM / 32, E_NUM), dim3(32, 8)>>>(w1);
    wconv2_kernel<<<dim3(H_DIM / 32, I_DIM / 32, E_NUM), dim3(32, 8)>>>(w2);

    dim3 g1(I_DIM / 128, T_TOKENS / 128, E_NUM);
    gemm1_kernel<<<g1, 512, SMEM_BYTES>>>(b1);

    dim3 g2(H_DIM / 128, T_TOKENS / 128, E_NUM);
    gemm2_kernel<<<g2, 512, SMEM_BYTES>>>(b2, out);
}

// round 13
// speedup vs baseline: 1.1805x; 1.0412x over previous
#include <cuda_runtime.h>
#include <cuda_fp16.h>
#include <cstdint>
#include <math.h>

#define T_TOKENS 8192
#define H_DIM    512
#define I_DIM    1024
#define E_NUM    8
#define CAP      T_TOKENS                // per-expert capacity
#define KC       64                      // K elems per stage (128B rows)

// ---------------- smem layout -------------------------------------------------
// per stage: 2 tiles (A, B), each 128 rows x 64 fp16, row stride 144B.
#define ROWB      144
#define TILE_SZ   (128 * ROWB)           // 18432 B
#define OFF_A     0
#define OFF_B     TILE_SZ
#define STG_BYTES (2 * TILE_SZ)          // 36864 B
#define NSTAGE    3
#define SMEM_BYTES (NSTAGE * STG_BYTES)  // 110592 B -> 2 CTAs/SM (221184 < 228KB)

// ---------------- PTX helpers ---------------------------------------------------
__device__ __forceinline__ uint32_t smem_to_u32(const void* p) {
    uint32_t a;
    asm("{ .reg .u64 t; cvta.to.shared.u64 t, %1; cvt.u32.u64 %0, t; }" : "=r"(a) : "l"(p));
    return a;
}
__device__ __forceinline__ void cp16(uint32_t s, const void* g) {
    asm volatile("cp.async.cg.shared.global [%0], [%1], 16;" :: "r"(s), "l"(g));
}
#define CP_COMMIT() asm volatile("cp.async.commit_group;" ::: "memory")
#define CP_WAIT1()  asm volatile("cp.async.wait_group 1;" ::: "memory")
#define CP_WAIT0()  asm volatile("cp.async.wait_group 0;" ::: "memory")

__device__ __forceinline__ void ldsm4(uint32_t* r, uint32_t a) {
    asm volatile("ldmatrix.sync.aligned.m8n8.x4.shared.b16 {%0,%1,%2,%3}, [%4];"
        : "=r"(r[0]), "=r"(r[1]), "=r"(r[2]), "=r"(r[3]) : "r"(a));
}
__device__ __forceinline__ void mma_f16(float* c, const uint32_t* a, const uint32_t* b) {
    asm volatile("mma.sync.aligned.m16n8k16.row.col.f32.f16.f16.f32 "
        "{%0,%1,%2,%3}, {%4,%5,%6,%7}, {%8,%9}, {%0,%1,%2,%3};"
        : "+f"(c[0]), "+f"(c[1]), "+f"(c[2]), "+f"(c[3])
        : "r"(a[0]), "r"(a[1]), "r"(a[2]), "r"(a[3]), "r"(b[0]), "r"(b[1]));
}

// ---------------- scratch (device globals) -------------------------------------
__device__ int   g_count[E_NUM];
__device__ int   g_list_tok[E_NUM * CAP];
__device__ float g_list_w[E_NUM * CAP];

__device__ __half g_xh[(size_t)T_TOKENS * H_DIM];
__device__ __half g_w1t[(size_t)E_NUM * I_DIM * H_DIM];   // [e][n=I][k=H]
__device__ __half g_w2t[(size_t)E_NUM * H_DIM * I_DIM];   // [e][n=H][k=I]
__device__ __half g_h[(size_t)E_NUM * CAP * I_DIM];

// ------- router (fused: logits, top-2, x->fp16, direct scatter) -----------------
__global__ void router_kernel(const float* __restrict__ x,
                              const float* __restrict__ gw,
                              float* __restrict__ logits_out) {
    int tid = threadIdx.x;
    int warp = tid >> 5, lane = tid & 31;
    int t = blockIdx.x * 8 + warp;

    float xr[16];
    #pragma unroll
    for (int j = 0; j < 16; j++) xr[j] = x[(size_t)t * H_DIM + lane + 32 * j];

    #pragma unroll
    for (int j = 0; j < 16; j++)
        g_xh[(size_t)t * H_DIM + lane + 32 * j] = __float2half_rn(xr[j]);

    float lg[E_NUM];
    #pragma unroll
    for (int e = 0; e < E_NUM; e++) {
        float s = 0.f;
        const float* g = gw + (size_t)e * H_DIM + lane;
        #pragma unroll
        for (int j = 0; j < 16; j++) s = fmaf(xr[j], g[32 * j], s);
        #pragma unroll
        for (int o = 16; o; o >>= 1) s += __shfl_xor_sync(0xffffffffu, s, o);
        lg[e] = s;
    }
    if (lane == 0) {
        float m = lg[0];
        #pragma unroll
        for (int e = 1; e < E_NUM; e++) m = fmaxf(m, lg[e]);
        float p[E_NUM], sum = 0.f;
        #pragma unroll
        for (int e = 0; e < E_NUM; e++) { p[e] = expf(lg[e] - m); sum += p[e]; }
        float inv = 1.f / sum;
        #pragma unroll
        for (int e = 0; e < E_NUM; e++) {
            p[e] *= inv;
            logits_out[(size_t)t * E_NUM + e] = lg[e];
        }
        int i0 = 0;
        #pragma unroll
        for (int e = 1; e < E_NUM; e++) if (p[e] > p[i0]) i0 = e;
        int i1 = (i0 == 0) ? 1 : 0;
        #pragma unroll
        for (int e = 0; e < E_NUM; e++) if (e != i1 && e != i0 && p[e] > p[i1]) i1 = e;
        float w0 = p[i0], w1 = p[i1];
        float s2 = w0 + w1 + 1e-20f;
        w0 = (w0 / s2) * 0.5f;
        w1 = (w1 / s2) * 0.5f;
        int p0 = atomicAdd(&g_count[i0], 1);
        g_list_tok[i0 * CAP + p0] = t;  g_list_w[i0 * CAP + p0] = w0;
        int p1 = atomicAdd(&g_count[i1], 1);
        g_list_tok[i1 * CAP + p1] = t;  g_list_w[i1 * CAP + p1] = w1;
    }
}

// ---------------- weight convert+transpose -> fp16 -------------------------------
__device__ __forceinline__ void wconv_body(const float* __restrict__ W,
                                           __half* __restrict__ wh,
                                           int K, int N) {
    __shared__ float s[32][33];
    int e = blockIdx.z;
    int k0 = blockIdx.y * 32, n0 = blockIdx.x * 32;
    const float* src = W + (size_t)e * K * N;
    int tx = threadIdx.x, ty = threadIdx.y;
    #pragma unroll
    for (int i = 0; i < 4; i++)
        s[ty + 8 * i][tx] = src[(size_t)(k0 + ty + 8 * i) * N + n0 + tx];
    __syncthreads();
    size_t ob = (size_t)e * N * K;
    #pragma unroll
    for (int i = 0; i < 4; i++) {
        int n = n0 + ty + 8 * i;
        wh[ob + (size_t)n * K + k0 + tx] = __float2half_rn(s[tx][ty + 8 * i]);
    }
}
__global__ void wconv1_kernel(const float* __restrict__ W) { wconv_body(W, g_w1t, H_DIM, I_DIM); }
__global__ void wconv2_kernel(const float* __restrict__ W) { wconv_body(W, g_w2t, I_DIM, H_DIM); }

// ---------------- GEMM core ------------------------------------------------------
struct LoadCtx {
    const char *aP, *bP;
    uint32_t sRow, gOff, smem0;
};

__device__ __forceinline__ void issue_stage(const LoadCtx& L, int s, int k0elem) {
    uint32_t sb = L.smem0 + s * STG_BYTES + L.sRow;
    size_t gk = (size_t)k0elem * 2 + L.gOff;
    cp16(sb + OFF_A,      L.aP + gk);
    cp16(sb + OFF_A + 16, L.aP + gk + 16);
    cp16(sb + OFF_B,      L.bP + gk);
    cp16(sb + OFF_B + 16, L.bP + gk + 16);
}

__device__ __forceinline__ void compute_stage(uint32_t sb,
        const uint32_t* aOff, const uint32_t* bOff, float acc[2][4][4]) {
    #pragma unroll
    for (int ks = 0; ks < 4; ks++) {
        uint32_t a[2][4], b[2][4];
        #pragma unroll
        for (int mi = 0; mi < 2; mi++)
            ldsm4(a[mi], sb + OFF_A + aOff[mi] + ks * 32);
        #pragma unroll
        for (int nt = 0; nt < 2; nt++)
            ldsm4(b[nt], sb + OFF_B + bOff[nt] + ks * 32);
        #pragma unroll
        for (int mi = 0; mi < 2; mi++) {
            #pragma unroll
            for (int ni = 0; ni < 4; ni++) {
                int nt = ni >> 1, j = ni & 1;
                uint32_t bf[2] = { b[nt][j], b[nt][j + 2] };
                mma_f16(acc[mi][ni], a[mi], bf);
            }
        }
    }
}

// ---------------- GEMM1: h = relu(gather(x) @ W1t + b1) -> fp16 ------------------
__global__ __launch_bounds__(512, 2) void gemm1_kernel(const float* __restrict__ b1) {
    extern __shared__ char smem[];
    const int e = blockIdx.z;
    const int cnt = g_count[e];
    const int m_base = blockIdx.y * 128;
    if (m_base >= cnt) return;
    const int off = e * CAP;
    const int n_base = blockIdx.x * 128;
    const int tid = threadIdx.x;
    const int w = tid >> 5, lane = tid & 31;
    const int wm = w & 3, wn = w >> 2;

    LoadCtx L;
    {
        int rowIdx = tid >> 2;
        int gm = m_base + rowIdx;
        int tok = g_list_tok[off + ((gm < cnt) ? gm : 0)];
        L.aP = (const char*)(g_xh + (size_t)tok * H_DIM);
        size_t rB = ((size_t)e * I_DIM + (n_base + rowIdx)) * H_DIM;
        L.bP = (const char*)(g_w1t + rB);
        L.gOff = (tid & 3) * 32;
        L.sRow = (uint32_t)rowIdx * ROWB + L.gOff;
        L.smem0 = smem_to_u32(smem);
    }

    uint32_t aOff[2], bOff[2];
    {
        int mat = lane >> 3, lr = lane & 7;
        uint32_t kb = (uint32_t)(lane >> 4) * 16;
        #pragma unroll
        for (int mi = 0; mi < 2; mi++)
            aOff[mi] = (uint32_t)(wm * 32 + mi * 16 + ((mat & 1) << 3) + lr) * ROWB + kb;
        #pragma unroll
        for (int nt = 0; nt < 2; nt++)
            bOff[nt] = (uint32_t)(wn * 32 + nt * 16 + ((mat & 1) << 3) + lr) * ROWB + kb;
    }

    float acc[2][4][4] = {};

    const int NC = H_DIM / KC;   // 8
    issue_stage(L, 0, 0);   CP_COMMIT();
    issue_stage(L, 1, KC);  CP_COMMIT();
    for (int c = 0; c < NC; c++) {
        if (c + 2 < NC) CP_WAIT1(); else CP_WAIT0();
        __syncthreads();
        if (c + 2 < NC) { issue_stage(L, (c + 2) % NSTAGE, (c + 2) * KC); CP_COMMIT(); }
        compute_stage(L.smem0 + (c % NSTAGE) * STG_BYTES, aOff, bOff, acc);
    }

    int qrow = lane >> 2, qcol = (lane & 3) * 2;
    #pragma unroll
    for (int mi = 0; mi < 2; mi++) {
        #pragma unroll
        for (int half = 0; half < 2; half++) {
            int row = wm * 32 + mi * 16 + qrow + half * 8;
            int gm = m_base + row;
            if (gm >= cnt) continue;
            size_t pair = (size_t)(off + gm);
            #pragma unroll
            for (int ni = 0; ni < 4; ni++) {
                int n = n_base + wn * 32 + ni * 8 + qcol;
                float v0 = fmaxf(acc[mi][ni][half * 2 + 0] + b1[e * I_DIM + n],     0.f);
                float v1 = fmaxf(acc[mi][ni][half * 2 + 1] + b1[e * I_DIM + n + 1], 0.f);
                __half2 hp = __floats2half2_rn(v0, v1);
                *reinterpret_cast<__half2*>(g_h + pair * I_DIM + n) = hp;
            }
        }
    }
}

// ---------------- GEMM2: out[tok] += wgt * (h @ W2t + b2) ------------------------
__global__ __launch_bounds__(512, 2) void gemm2_kernel(const float* __restrict__ b2,
                                                       float* __restrict__ out) {
    extern __shared__ char smem[];
    const int e = blockIdx.z;
    const int cnt = g_count[e];
    const int m_base = blockIdx.y * 128;
    if (m_base >= cnt) return;
    const int off = e * CAP;
    const int n_base = blockIdx.x * 128;
    const int tid = threadIdx.x;
    const int w = tid >> 5, lane = tid & 31;
    const int wm = w & 3, wn = w >> 2;

    LoadCtx L;
    {
        int rowIdx = tid >> 2;
        int gm = m_base + rowIdx;
        size_t pr = (size_t)(off + ((gm < cnt) ? gm : 0));
        L.aP = (const char*)(g_h + pr * I_DIM);
        size_t rB = ((size_t)e * H_DIM + (n_base + rowIdx)) * I_DIM;
        L.bP = (const char*)(g_w2t + rB);
        L.gOff = (tid & 3) * 32;
        L.sRow = (uint32_t)rowIdx * ROWB + L.gOff;
        L.smem0 = smem_to_u32(smem);
    }

    uint32_t aOff[2], bOff[2];
    {
        int mat = lane >> 3, lr = lane & 7;
        uint32_t kb = (uint32_t)(lane >> 4) * 16;
        #pragma unroll
        for (int mi = 0; mi < 2; mi++)
            aOff[mi] = (uint32_t)(wm * 32 + mi * 16 + ((mat & 1) << 3) + lr) * ROWB + kb;
        #pragma unroll
        for (int nt = 0; nt < 2; nt++)
            bOff[nt] = (uint32_t)(wn * 32 + nt * 16 + ((mat & 1) << 3) + lr) * ROWB + kb;
    }

    float acc[2][4][4] = {};

    const int NC = I_DIM / KC;   // 16
    issue_stage(L, 0, 0);   CP_COMMIT();
    issue_stage(L, 1, KC);  CP_COMMIT();
    for (int c = 0; c < NC; c++) {
        if (c + 2 < NC) CP_WAIT1(); else CP_WAIT0();
        __syncthreads();
        if (c + 2 < NC) { issue_stage(L, (c + 2) % NSTAGE, (c + 2) * KC); CP_COMMIT(); }
        compute_stage(L.smem0 + (c % NSTAGE) * STG_BYTES, aOff, bOff, acc);
    }

    int qrow = lane >> 2, qcol = (lane & 3) * 2;
    #pragma unroll
    for (int mi = 0; mi < 2; mi++) {
        #pragma unroll
        for (int half = 0; half < 2; half++) {
            int row = wm * 32 + mi * 16 + qrow + half * 8;
            int gm = m_base + row;
            if (gm >= cnt) continue;
            int tok = g_list_tok[off + gm];
            float wgt = g_list_w[off + gm];
            float* dst = out + (size_t)tok * H_DIM;
            #pragma unroll
            for (int ni = 0; ni < 4; ni++) {
                int n = n_base + wn * 32 + ni * 8 + qcol;
                atomicAdd(&dst[n],     wgt * (acc[mi][ni][half * 2 + 0] + b2[e * H_DIM + n]));
                atomicAdd(&dst[n + 1], wgt * (acc[mi][ni][half * 2 + 1] + b2[e * H_DIM + n + 1]));
            }
        }
    }
}

// ---------------- launch ----------------------------------------------------------
extern "C" void kernel_launch(void* const* d_in, const int* in_sizes, int n_in,
                              void* d_out, int out_size) {
    const float* x  = (const float*)d_in[0];
    const float* gw = (const float*)d_in[1];
    const float* w1 = (const float*)d_in[2];
    const float* b1 = (const float*)d_in[3];
    const float* w2 = (const float*)d_in[4];
    const float* b2 = (const float*)d_in[5];
    float* out = (float*)d_out;
    float* logits = out + (size_t)T_TOKENS * H_DIM;

    cudaFuncSetAttribute(gemm1_kernel, cudaFuncAttributeMaxDynamicSharedMemorySize, SMEM_BYTES);
    cudaFuncSetAttribute(gemm2_kernel, cudaFuncAttributeMaxDynamicSharedMemorySize, SMEM_BYTES);

    cudaMemsetAsync(out, 0, (size_t)T_TOKENS * H_DIM * sizeof(float), 0);
    void* cnt_ptr = nullptr;
    cudaGetSymbolAddress(&cnt_ptr, g_count);
    cudaMemsetAsync(cnt_ptr, 0, E_NUM * sizeof(int), 0);

    router_kernel<<<T_TOKENS / 8, 256>>>(x, gw, logits);

    wconv1_kernel<<<dim3(I_DIM / 32, H_DIM / 32, E_NUM), dim3(32, 8)>>>(w1);
    wconv2_kernel<<<dim3(H_DIM / 32, I_DIM / 32, E_NUM), dim3(32, 8)>>>(w2);

    dim3 g1(I_DIM / 128, T_TOKENS / 128, E_NUM);
    gemm1_kernel<<<g1, 512, SMEM_BYTES>>>(b1);

    dim3 g2(H_DIM / 128, T_TOKENS / 128, E_NUM);
    gemm2_kernel<<<g2, 512, SMEM_BYTES>>>(b2, out);
}

// round 14
// speedup vs baseline: 1.2311x; 1.0428x over previous
#include <cuda_runtime.h>
#include <cuda_fp16.h>
#include <cstdint>
#include <math.h>

#define T_TOKENS 8192
#define H_DIM    512
#define I_DIM    1024
#define E_NUM    8
#define CAP      T_TOKENS                // per-expert capacity
#define KC       64                      // K elems per stage (128B rows)

// ---------------- smem layout -------------------------------------------------
#define ROWB      144
#define TILE_SZ   (128 * ROWB)           // 18432 B
#define OFF_A     0
#define OFF_B     TILE_SZ
#define STG_BYTES (2 * TILE_SZ)          // 36864 B
#define NSTAGE    3
#define SMEM_BYTES (NSTAGE * STG_BYTES)  // 110592 B -> 2 CTAs/SM

// ---------------- PTX helpers ---------------------------------------------------
__device__ __forceinline__ uint32_t smem_to_u32(const void* p) {
    uint32_t a;
    asm("{ .reg .u64 t; cvta.to.shared.u64 t, %1; cvt.u32.u64 %0, t; }" : "=r"(a) : "l"(p));
    return a;
}
__device__ __forceinline__ void cp16(uint32_t s, const void* g) {
    asm volatile("cp.async.cg.shared.global [%0], [%1], 16;" :: "r"(s), "l"(g));
}
#define CP_COMMIT() asm volatile("cp.async.commit_group;" ::: "memory")
#define CP_WAIT1()  asm volatile("cp.async.wait_group 1;" ::: "memory")
#define CP_WAIT0()  asm volatile("cp.async.wait_group 0;" ::: "memory")

__device__ __forceinline__ void ldsm4(uint32_t* r, uint32_t a) {
    asm volatile("ldmatrix.sync.aligned.m8n8.x4.shared.b16 {%0,%1,%2,%3}, [%4];"
        : "=r"(r[0]), "=r"(r[1]), "=r"(r[2]), "=r"(r[3]) : "r"(a));
}
__device__ __forceinline__ void mma_f16(float* c, const uint32_t* a, const uint32_t* b) {
    asm volatile("mma.sync.aligned.m16n8k16.row.col.f32.f16.f16.f32 "
        "{%0,%1,%2,%3}, {%4,%5,%6,%7}, {%8,%9}, {%0,%1,%2,%3};"
        : "+f"(c[0]), "+f"(c[1]), "+f"(c[2]), "+f"(c[3])
        : "r"(a[0]), "r"(a[1]), "r"(a[2]), "r"(a[3]), "r"(b[0]), "r"(b[1]));
}

// ---------------- scratch (device globals) -------------------------------------
__device__ int   g_count[E_NUM];
__device__ int   g_list_tok[E_NUM * CAP];
__device__ float g_list_w[E_NUM * CAP];

__device__ __half g_xh[(size_t)T_TOKENS * H_DIM];
__device__ __half g_w1t[(size_t)E_NUM * I_DIM * H_DIM];   // [e][n=I][k=H]
__device__ __half g_w2t[(size_t)E_NUM * H_DIM * I_DIM];   // [e][n=H][k=I]
__device__ __half g_h[(size_t)E_NUM * CAP * I_DIM];

// ---------------- fused aux kernel: wconv1 | wconv2 | router ---------------------
// grid.x = 1024 (wconv1) + 1024 (wconv2) + 1024 (router), 256 threads each.

__device__ __forceinline__ void wconv_tile(const float* __restrict__ W,
                                           __half* __restrict__ wh,
                                           int K, int N, int e, int k0, int n0,
                                           float (*s)[65]) {
    int tid = threadIdx.x;
    const float* src = W + (size_t)e * K * N + (size_t)k0 * N + n0;
    // load 64 rows x 64 cols as float4 (4 per thread)
    int r = tid >> 2, c = tid & 3;
    const float4* row4 = reinterpret_cast<const float4*>(src + (size_t)r * N);
    #pragma unroll
    for (int i = 0; i < 4; i++) {
        int c4 = c + 4 * i;           // 0..15
        float4 v = row4[c4];
        s[r][c4 * 4 + 0] = v.x;
        s[r][c4 * 4 + 1] = v.y;
        s[r][c4 * 4 + 2] = v.z;
        s[r][c4 * 4 + 3] = v.w;
    }
    __syncthreads();
    // store transposed: 8 halves (16B) per task, 2 tasks per thread
    size_t ob = (size_t)e * N * K + k0;
    #pragma unroll
    for (int q = 0; q < 2; q++) {
        int t = tid + q * 256;        // 0..511
        int n = t & 63;
        int kb = t >> 6;              // 0..7
        __half hx[8];
        #pragma unroll
        for (int j = 0; j < 8; j++)
            hx[j] = __float2half_rn(s[kb * 8 + j][n]);
        *reinterpret_cast<uint4*>(wh + ob + (size_t)(n0 + n) * K + kb * 8) =
            *reinterpret_cast<uint4*>(hx);
    }
}

__global__ void aux_kernel(const float* __restrict__ x,
                           const float* __restrict__ gw,
                           const float* __restrict__ w1,
                           const float* __restrict__ w2,
                           float* __restrict__ logits_out) {
    __shared__ float s[64][65];
    int bid = blockIdx.x;

    if (bid < 1024) {
        // wconv1: K=H_DIM(512), N=I_DIM(1024); tiles 16(n) x 8(k) per expert
        int e = bid >> 7, t = bid & 127;
        int n0 = (t & 15) * 64, k0 = (t >> 4) * 64;
        wconv_tile(w1, g_w1t, H_DIM, I_DIM, e, k0, n0, s);
        return;
    }
    if (bid < 2048) {
        // wconv2: K=I_DIM(1024), N=H_DIM(512); tiles 8(n) x 16(k) per expert
        int r = bid - 1024;
        int e = r >> 7, t = r & 127;
        int n0 = (t & 7) * 64, k0 = (t >> 3) * 64;
        wconv_tile(w2, g_w2t, I_DIM, H_DIM, e, k0, n0, s);
        return;
    }

    // ---- router ----
    int rb = bid - 2048;               // 0..1023
    int tid = threadIdx.x;
    int warp = tid >> 5, lane = tid & 31;
    int t = rb * 8 + warp;

    float xr[16];
    #pragma unroll
    for (int j = 0; j < 16; j++) xr[j] = x[(size_t)t * H_DIM + lane + 32 * j];

    #pragma unroll
    for (int j = 0; j < 16; j++)
        g_xh[(size_t)t * H_DIM + lane + 32 * j] = __float2half_rn(xr[j]);

    float lg[E_NUM];
    #pragma unroll
    for (int e = 0; e < E_NUM; e++) {
        float sum = 0.f;
        const float* g = gw + (size_t)e * H_DIM + lane;
        #pragma unroll
        for (int j = 0; j < 16; j++) sum = fmaf(xr[j], g[32 * j], sum);
        #pragma unroll
        for (int o = 16; o; o >>= 1) sum += __shfl_xor_sync(0xffffffffu, sum, o);
        lg[e] = sum;
    }
    if (lane == 0) {
        float m = lg[0];
        #pragma unroll
        for (int e = 1; e < E_NUM; e++) m = fmaxf(m, lg[e]);
        float p[E_NUM], sum = 0.f;
        #pragma unroll
        for (int e = 0; e < E_NUM; e++) { p[e] = expf(lg[e] - m); sum += p[e]; }
        float inv = 1.f / sum;
        #pragma unroll
        for (int e = 0; e < E_NUM; e++) {
            p[e] *= inv;
            logits_out[(size_t)t * E_NUM + e] = lg[e];
        }
        int i0 = 0;
        #pragma unroll
        for (int e = 1; e < E_NUM; e++) if (p[e] > p[i0]) i0 = e;
        int i1 = (i0 == 0) ? 1 : 0;
        #pragma unroll
        for (int e = 0; e < E_NUM; e++) if (e != i1 && e != i0 && p[e] > p[i1]) i1 = e;
        float w0 = p[i0], w1v = p[i1];
        float s2 = w0 + w1v + 1e-20f;
        w0 = (w0 / s2) * 0.5f;
        w1v = (w1v / s2) * 0.5f;
        int p0 = atomicAdd(&g_count[i0], 1);
        g_list_tok[i0 * CAP + p0] = t;  g_list_w[i0 * CAP + p0] = w0;
        int p1 = atomicAdd(&g_count[i1], 1);
        g_list_tok[i1 * CAP + p1] = t;  g_list_w[i1 * CAP + p1] = w1v;
    }
}

// ---------------- GEMM core ------------------------------------------------------
struct LoadCtx {
    const char *aP, *bP;
    uint32_t sRow, gOff, smem0;
};

__device__ __forceinline__ void issue_stage(const LoadCtx& L, int s, int k0elem) {
    uint32_t sb = L.smem0 + s * STG_BYTES + L.sRow;
    size_t gk = (size_t)k0elem * 2 + L.gOff;
    cp16(sb + OFF_A,      L.aP + gk);
    cp16(sb + OFF_A + 16, L.aP + gk + 16);
    cp16(sb + OFF_B,      L.bP + gk);
    cp16(sb + OFF_B + 16, L.bP + gk + 16);
}

__device__ __forceinline__ void compute_stage(uint32_t sb,
        const uint32_t* aOff, const uint32_t* bOff, float acc[2][4][4]) {
    #pragma unroll
    for (int ks = 0; ks < 4; ks++) {
        uint32_t a[2][4], b[2][4];
        #pragma unroll
        for (int mi = 0; mi < 2; mi++)
            ldsm4(a[mi], sb + OFF_A + aOff[mi] + ks * 32);
        #pragma unroll
        for (int nt = 0; nt < 2; nt++)
            ldsm4(b[nt], sb + OFF_B + bOff[nt] + ks * 32);
        #pragma unroll
        for (int mi = 0; mi < 2; mi++) {
            #pragma unroll
            for (int ni = 0; ni < 4; ni++) {
                int nt = ni >> 1, j = ni & 1;
                uint32_t bf[2] = { b[nt][j], b[nt][j + 2] };
                mma_f16(acc[mi][ni], a[mi], bf);
            }
        }
    }
}

// ---------------- GEMM1: h = relu(gather(x) @ W1t + b1) -> fp16 ------------------
__global__ __launch_bounds__(512, 2) void gemm1_kernel(const float* __restrict__ b1) {
    extern __shared__ char smem[];
    const int e = blockIdx.z;
    const int cnt = g_count[e];
    const int m_base = blockIdx.y * 128;
    if (m_base >= cnt) return;
    const int off = e * CAP;
    const int n_base = blockIdx.x * 128;
    const int tid = threadIdx.x;
    const int w = tid >> 5, lane = tid & 31;
    const int wm = w & 3, wn = w >> 2;

    LoadCtx L;
    {
        int rowIdx = tid >> 2;
        int gm = m_base + rowIdx;
        int tok = g_list_tok[off + ((gm < cnt) ? gm : 0)];
        L.aP = (const char*)(g_xh + (size_t)tok * H_DIM);
        size_t rB = ((size_t)e * I_DIM + (n_base + rowIdx)) * H_DIM;
        L.bP = (const char*)(g_w1t + rB);
        L.gOff = (tid & 3) * 32;
        L.sRow = (uint32_t)rowIdx * ROWB + L.gOff;
        L.smem0 = smem_to_u32(smem);
    }

    uint32_t aOff[2], bOff[2];
    {
        int mat = lane >> 3, lr = lane & 7;
        uint32_t kb = (uint32_t)(lane >> 4) * 16;
        #pragma unroll
        for (int mi = 0; mi < 2; mi++)
            aOff[mi] = (uint32_t)(wm * 32 + mi * 16 + ((mat & 1) << 3) + lr) * ROWB + kb;
        #pragma unroll
        for (int nt = 0; nt < 2; nt++)
            bOff[nt] = (uint32_t)(wn * 32 + nt * 16 + ((mat & 1) << 3) + lr) * ROWB + kb;
    }

    float acc[2][4][4] = {};

    const int NC = H_DIM / KC;   // 8
    issue_stage(L, 0, 0);   CP_COMMIT();
    issue_stage(L, 1, KC);  CP_COMMIT();
    for (int c = 0; c < NC; c++) {
        if (c + 2 < NC) CP_WAIT1(); else CP_WAIT0();
        __syncthreads();
        if (c + 2 < NC) { issue_stage(L, (c + 2) % NSTAGE, (c + 2) * KC); CP_COMMIT(); }
        compute_stage(L.smem0 + (c % NSTAGE) * STG_BYTES, aOff, bOff, acc);
    }

    int qrow = lane >> 2, qcol = (lane & 3) * 2;
    #pragma unroll
    for (int mi = 0; mi < 2; mi++) {
        #pragma unroll
        for (int half = 0; half < 2; half++) {
            int row = wm * 32 + mi * 16 + qrow + half * 8;
            int gm = m_base + row;
            if (gm >= cnt) continue;
            size_t pair = (size_t)(off + gm);
            #pragma unroll
            for (int ni = 0; ni < 4; ni++) {
                int n = n_base + wn * 32 + ni * 8 + qcol;
                float v0 = fmaxf(acc[mi][ni][half * 2 + 0] + b1[e * I_DIM + n],     0.f);
                float v1 = fmaxf(acc[mi][ni][half * 2 + 1] + b1[e * I_DIM + n + 1], 0.f);
                __half2 hp = __floats2half2_rn(v0, v1);
                *reinterpret_cast<__half2*>(g_h + pair * I_DIM + n) = hp;
            }
        }
    }
}

// ---------------- GEMM2: out[tok] += wgt * (h @ W2t + b2) ------------------------
__global__ __launch_bounds__(512, 2) void gemm2_kernel(const float* __restrict__ b2,
                                                       float* __restrict__ out) {
    extern __shared__ char smem[];
    const int e = blockIdx.z;
    const int cnt = g_count[e];
    const int m_base = blockIdx.y * 128;
    if (m_base >= cnt) return;
    const int off = e * CAP;
    const int n_base = blockIdx.x * 128;
    const int tid = threadIdx.x;
    const int w = tid >> 5, lane = tid & 31;
    const int wm = w & 3, wn = w >> 2;

    LoadCtx L;
    {
        int rowIdx = tid >> 2;
        int gm = m_base + rowIdx;
        size_t pr = (size_t)(off + ((gm < cnt) ? gm : 0));
        L.aP = (const char*)(g_h + pr * I_DIM);
        size_t rB = ((size_t)e * H_DIM + (n_base + rowIdx)) * I_DIM;
        L.bP = (const char*)(g_w2t + rB);
        L.gOff = (tid & 3) * 32;
        L.sRow = (uint32_t)rowIdx * ROWB + L.gOff;
        L.smem0 = smem_to_u32(smem);
    }

    uint32_t aOff[2], bOff[2];
    {
        int mat = lane >> 3, lr = lane & 7;
        uint32_t kb = (uint32_t)(lane >> 4) * 16;
        #pragma unroll
        for (int mi = 0; mi < 2; mi++)
            aOff[mi] = (uint32_t)(wm * 32 + mi * 16 + ((mat & 1) << 3) + lr) * ROWB + kb;
        #pragma unroll
        for (int nt = 0; nt < 2; nt++)
            bOff[nt] = (uint32_t)(wn * 32 + nt * 16 + ((mat & 1) << 3) + lr) * ROWB + kb;
    }

    float acc[2][4][4] = {};

    const int NC = I_DIM / KC;   // 16
    issue_stage(L, 0, 0);   CP_COMMIT();
    issue_stage(L, 1, KC);  CP_COMMIT();
    for (int c = 0; c < NC; c++) {
        if (c + 2 < NC) CP_WAIT1(); else CP_WAIT0();
        __syncthreads();
        if (c + 2 < NC) { issue_stage(L, (c + 2) % NSTAGE, (c + 2) * KC); CP_COMMIT(); }
        compute_stage(L.smem0 + (c % NSTAGE) * STG_BYTES, aOff, bOff, acc);
    }

    int qrow = lane >> 2, qcol = (lane & 3) * 2;
    #pragma unroll
    for (int mi = 0; mi < 2; mi++) {
        #pragma unroll
        for (int half = 0; half < 2; half++) {
            int row = wm * 32 + mi * 16 + qrow + half * 8;
            int gm = m_base + row;
            if (gm >= cnt) continue;
            int tok = g_list_tok[off + gm];
            float wgt = g_list_w[off + gm];
            float* dst = out + (size_t)tok * H_DIM;
            #pragma unroll
            for (int ni = 0; ni < 4; ni++) {
                int n = n_base + wn * 32 + ni * 8 + qcol;
                atomicAdd(&dst[n],     wgt * (acc[mi][ni][half * 2 + 0] + b2[e * H_DIM + n]));
                atomicAdd(&dst[n + 1], wgt * (acc[mi][ni][half * 2 + 1] + b2[e * H_DIM + n + 1]));
            }
        }
    }
}

// ---------------- launch ----------------------------------------------------------
extern "C" void kernel_launch(void* const* d_in, const int* in_sizes, int n_in,
                              void* d_out, int out_size) {
    const float* x  = (const float*)d_in[0];
    const float* gw = (const float*)d_in[1];
    const float* w1 = (const float*)d_in[2];
    const float* b1 = (const float*)d_in[3];
    const float* w2 = (const float*)d_in[4];
    const float* b2 = (const float*)d_in[5];
    float* out = (float*)d_out;
    float* logits = out + (size_t)T_TOKENS * H_DIM;

    cudaFuncSetAttribute(gemm1_kernel, cudaFuncAttributeMaxDynamicSharedMemorySize, SMEM_BYTES);
    cudaFuncSetAttribute(gemm2_kernel, cudaFuncAttributeMaxDynamicSharedMemorySize, SMEM_BYTES);

    cudaMemsetAsync(out, 0, (size_t)T_TOKENS * H_DIM * sizeof(float), 0);
    void* cnt_ptr = nullptr;
    cudaGetSymbolAddress(&cnt_ptr, g_count);
    cudaMemsetAsync(cnt_ptr, 0, E_NUM * sizeof(int), 0);

    // fused aux: 1024 wconv1 + 1024 wconv2 + 1024 router blocks
    aux_kernel<<<3072, 256>>>(x, gw, w1, w2, logits);

    dim3 g1(I_DIM / 128, T_TOKENS / 128, E_NUM);
    gemm1_kernel<<<g1, 512, SMEM_BYTES>>>(b1);

    dim3 g2(H_DIM / 128, T_TOKENS / 128, E_NUM);
    gemm2_kernel<<<g2, 512, SMEM_BYTES>>>(b2, out);
}

// round 15
// speedup vs baseline: 1.2445x; 1.0109x over previous
#include <cuda_runtime.h>
#include <cuda_fp16.h>
#include <cstdint>
#include <math.h>

#define T_TOKENS 8192
#define H_DIM    512
#define I_DIM    1024
#define E_NUM    8
#define CAP      T_TOKENS                // per-expert capacity
#define KC       64                      // K elems per stage (128B rows)

// ---------------- smem layout -------------------------------------------------
#define ROWB      144
#define TILE_SZ   (128 * ROWB)           // 18432 B
#define OFF_A     0
#define OFF_B     TILE_SZ
#define STG_BYTES (2 * TILE_SZ)          // 36864 B
#define NSTAGE    3
#define SMEM_BYTES (NSTAGE * STG_BYTES)  // 110592 B -> 2 CTAs/SM

// ---------------- PTX helpers ---------------------------------------------------
__device__ __forceinline__ uint32_t smem_to_u32(const void* p) {
    uint32_t a;
    asm("{ .reg .u64 t; cvta.to.shared.u64 t, %1; cvt.u32.u64 %0, t; }" : "=r"(a) : "l"(p));
    return a;
}
__device__ __forceinline__ void cp16(uint32_t s, const void* g) {
    asm volatile("cp.async.cg.shared.global [%0], [%1], 16;" :: "r"(s), "l"(g));
}
#define CP_COMMIT() asm volatile("cp.async.commit_group;" ::: "memory")
#define CP_WAIT1()  asm volatile("cp.async.wait_group 1;" ::: "memory")
#define CP_WAIT0()  asm volatile("cp.async.wait_group 0;" ::: "memory")

__device__ __forceinline__ void ldsm4(uint32_t* r, uint32_t a) {
    asm volatile("ldmatrix.sync.aligned.m8n8.x4.shared.b16 {%0,%1,%2,%3}, [%4];"
        : "=r"(r[0]), "=r"(r[1]), "=r"(r[2]), "=r"(r[3]) : "r"(a));
}
__device__ __forceinline__ void mma_f16(float* c, const uint32_t* a, const uint32_t* b) {
    asm volatile("mma.sync.aligned.m16n8k16.row.col.f32.f16.f16.f32 "
        "{%0,%1,%2,%3}, {%4,%5,%6,%7}, {%8,%9}, {%0,%1,%2,%3};"
        : "+f"(c[0]), "+f"(c[1]), "+f"(c[2]), "+f"(c[3])
        : "r"(a[0]), "r"(a[1]), "r"(a[2]), "r"(a[3]), "r"(b[0]), "r"(b[1]));
}

// ---------------- scratch (device globals) -------------------------------------
__device__ int   g_count[E_NUM];
__device__ int   g_list_tok[E_NUM * CAP];
__device__ float g_list_w[E_NUM * CAP];

__device__ __half g_xh[(size_t)T_TOKENS * H_DIM];
__device__ __half g_w1t[(size_t)E_NUM * I_DIM * H_DIM];   // [e][n=I][k=H]
__device__ __half g_w2t[(size_t)E_NUM * H_DIM * I_DIM];   // [e][n=H][k=I]
__device__ __half g_h[(size_t)E_NUM * CAP * I_DIM];

// ---------------- fused aux kernel: wconv1 | wconv2 | router ---------------------
// grid.x = 1024 (wconv1) + 1024 (wconv2) + 1024 (router), 256 threads each.

__device__ __forceinline__ void wconv_tile(const float* __restrict__ W,
                                           __half* __restrict__ wh,
                                           int K, int N, int e, int k0, int n0,
                                           float (*s)[65]) {
    int tid = threadIdx.x;
    const float* src = W + (size_t)e * K * N + (size_t)k0 * N + n0;
    // load 64 rows x 64 cols as float4 (4 per thread)
    int r = tid >> 2, c = tid & 3;
    const float4* row4 = reinterpret_cast<const float4*>(src + (size_t)r * N);
    #pragma unroll
    for (int i = 0; i < 4; i++) {
        int c4 = c + 4 * i;           // 0..15
        float4 v = row4[c4];
        s[r][c4 * 4 + 0] = v.x;
        s[r][c4 * 4 + 1] = v.y;
        s[r][c4 * 4 + 2] = v.z;
        s[r][c4 * 4 + 3] = v.w;
    }
    __syncthreads();
    // store transposed: kb fastest across threads -> each 8-thread group writes
    // one fully-contiguous 128B output row segment (coalesced full lines).
    size_t ob = (size_t)e * N * K + k0;
    #pragma unroll
    for (int q = 0; q < 2; q++) {
        int t = tid + q * 256;        // 0..511
        int kb = t & 7;               // 0..7, fastest
        int n  = t >> 3;              // 0..63
        __half hx[8];
        #pragma unroll
        for (int j = 0; j < 8; j++)
            hx[j] = __float2half_rn(s[kb * 8 + j][n]);
        *reinterpret_cast<uint4*>(wh + ob + (size_t)(n0 + n) * K + kb * 8) =
            *reinterpret_cast<uint4*>(hx);
    }
}

__global__ void aux_kernel(const float* __restrict__ x,
                           const float* __restrict__ gw,
                           const float* __restrict__ w1,
                           const float* __restrict__ w2,
                           float* __restrict__ logits_out) {
    __shared__ float s[64][65];
    int bid = blockIdx.x;

    if (bid < 1024) {
        // wconv1: K=H_DIM(512), N=I_DIM(1024); tiles 16(n) x 8(k) per expert
        int e = bid >> 7, t = bid & 127;
        int n0 = (t & 15) * 64, k0 = (t >> 4) * 64;
        wconv_tile(w1, g_w1t, H_DIM, I_DIM, e, k0, n0, s);
        return;
    }
    if (bid < 2048) {
        // wconv2: K=I_DIM(1024), N=H_DIM(512); tiles 8(n) x 16(k) per expert
        int r = bid - 1024;
        int e = r >> 7, t = r & 127;
        int n0 = (t & 7) * 64, k0 = (t >> 3) * 64;
        wconv_tile(w2, g_w2t, I_DIM, H_DIM, e, k0, n0, s);
        return;
    }

    // ---- router ----
    int rb = bid - 2048;               // 0..1023
    int tid = threadIdx.x;
    int warp = tid >> 5, lane = tid & 31;
    int t = rb * 8 + warp;

    float xr[16];
    #pragma unroll
    for (int j = 0; j < 16; j++) xr[j] = x[(size_t)t * H_DIM + lane + 32 * j];

    #pragma unroll
    for (int j = 0; j < 16; j++)
        g_xh[(size_t)t * H_DIM + lane + 32 * j] = __float2half_rn(xr[j]);

    float lg[E_NUM];
    #pragma unroll
    for (int e = 0; e < E_NUM; e++) {
        float sum = 0.f;
        const float* g = gw + (size_t)e * H_DIM + lane;
        #pragma unroll
        for (int j = 0; j < 16; j++) sum = fmaf(xr[j], g[32 * j], sum);
        #pragma unroll
        for (int o = 16; o; o >>= 1) sum += __shfl_xor_sync(0xffffffffu, sum, o);
        lg[e] = sum;
    }
    if (lane == 0) {
        float m = lg[0];
        #pragma unroll
        for (int e = 1; e < E_NUM; e++) m = fmaxf(m, lg[e]);
        float p[E_NUM], sum = 0.f;
        #pragma unroll
        for (int e = 0; e < E_NUM; e++) { p[e] = expf(lg[e] - m); sum += p[e]; }
        float inv = 1.f / sum;
        #pragma unroll
        for (int e = 0; e < E_NUM; e++) {
            p[e] *= inv;
            logits_out[(size_t)t * E_NUM + e] = lg[e];
        }
        int i0 = 0;
        #pragma unroll
        for (int e = 1; e < E_NUM; e++) if (p[e] > p[i0]) i0 = e;
        int i1 = (i0 == 0) ? 1 : 0;
        #pragma unroll
        for (int e = 0; e < E_NUM; e++) if (e != i1 && e != i0 && p[e] > p[i1]) i1 = e;
        float w0 = p[i0], w1v = p[i1];
        float s2 = w0 + w1v + 1e-20f;
        w0 = (w0 / s2) * 0.5f;
        w1v = (w1v / s2) * 0.5f;
        int p0 = atomicAdd(&g_count[i0], 1);
        g_list_tok[i0 * CAP + p0] = t;  g_list_w[i0 * CAP + p0] = w0;
        int p1 = atomicAdd(&g_count[i1], 1);
        g_list_tok[i1 * CAP + p1] = t;  g_list_w[i1 * CAP + p1] = w1v;
    }
}

// ---------------- GEMM core ------------------------------------------------------
struct LoadCtx {
    const char *aP, *bP;
    uint32_t sRow, gOff, smem0;
};

__device__ __forceinline__ void issue_stage(const LoadCtx& L, int s, int k0elem) {
    uint32_t sb = L.smem0 + s * STG_BYTES + L.sRow;
    size_t gk = (size_t)k0elem * 2 + L.gOff;
    cp16(sb + OFF_A,      L.aP + gk);
    cp16(sb + OFF_A + 16, L.aP + gk + 16);
    cp16(sb + OFF_B,      L.bP + gk);
    cp16(sb + OFF_B + 16, L.bP + gk + 16);
}

__device__ __forceinline__ void compute_stage(uint32_t sb,
        const uint32_t* aOff, const uint32_t* bOff, float acc[2][4][4]) {
    #pragma unroll
    for (int ks = 0; ks < 4; ks++) {
        uint32_t a[2][4], b[2][4];
        #pragma unroll
        for (int mi = 0; mi < 2; mi++)
            ldsm4(a[mi], sb + OFF_A + aOff[mi] + ks * 32);
        #pragma unroll
        for (int nt = 0; nt < 2; nt++)
            ldsm4(b[nt], sb + OFF_B + bOff[nt] + ks * 32);
        #pragma unroll
        for (int mi = 0; mi < 2; mi++) {
            #pragma unroll
            for (int ni = 0; ni < 4; ni++) {
                int nt = ni >> 1, j = ni & 1;
                uint32_t bf[2] = { b[nt][j], b[nt][j + 2] };
                mma_f16(acc[mi][ni], a[mi], bf);
            }
        }
    }
}

// ---------------- GEMM1: h = relu(gather(x) @ W1t + b1) -> fp16 ------------------
__global__ __launch_bounds__(512, 2) void gemm1_kernel(const float* __restrict__ b1) {
    extern __shared__ char smem[];
    const int e = blockIdx.z;
    const int cnt = g_count[e];
    const int m_base = blockIdx.y * 128;
    if (m_base >= cnt) return;
    const int off = e * CAP;
    const int n_base = blockIdx.x * 128;
    const int tid = threadIdx.x;
    const int w = tid >> 5, lane = tid & 31;
    const int wm = w & 3, wn = w >> 2;

    LoadCtx L;
    {
        int rowIdx = tid >> 2;
        int gm = m_base + rowIdx;
        int tok = g_list_tok[off + ((gm < cnt) ? gm : 0)];
        L.aP = (const char*)(g_xh + (size_t)tok * H_DIM);
        size_t rB = ((size_t)e * I_DIM + (n_base + rowIdx)) * H_DIM;
        L.bP = (const char*)(g_w1t + rB);
        L.gOff = (tid & 3) * 32;
        L.sRow = (uint32_t)rowIdx * ROWB + L.gOff;
        L.smem0 = smem_to_u32(smem);
    }

    uint32_t aOff[2], bOff[2];
    {
        int mat = lane >> 3, lr = lane & 7;
        uint32_t kb = (uint32_t)(lane >> 4) * 16;
        #pragma unroll
        for (int mi = 0; mi < 2; mi++)
            aOff[mi] = (uint32_t)(wm * 32 + mi * 16 + ((mat & 1) << 3) + lr) * ROWB + kb;
        #pragma unroll
        for (int nt = 0; nt < 2; nt++)
            bOff[nt] = (uint32_t)(wn * 32 + nt * 16 + ((mat & 1) << 3) + lr) * ROWB + kb;
    }

    float acc[2][4][4] = {};

    const int NC = H_DIM / KC;   // 8
    issue_stage(L, 0, 0);   CP_COMMIT();
    issue_stage(L, 1, KC);  CP_COMMIT();
    for (int c = 0; c < NC; c++) {
        if (c + 2 < NC) CP_WAIT1(); else CP_WAIT0();
        __syncthreads();
        if (c + 2 < NC) { issue_stage(L, (c + 2) % NSTAGE, (c + 2) * KC); CP_COMMIT(); }
        compute_stage(L.smem0 + (c % NSTAGE) * STG_BYTES, aOff, bOff, acc);
    }

    int qrow = lane >> 2, qcol = (lane & 3) * 2;
    #pragma unroll
    for (int mi = 0; mi < 2; mi++) {
        #pragma unroll
        for (int half = 0; half < 2; half++) {
            int row = wm * 32 + mi * 16 + qrow + half * 8;
            int gm = m_base + row;
            if (gm >= cnt) continue;
            size_t pair = (size_t)(off + gm);
            #pragma unroll
            for (int ni = 0; ni < 4; ni++) {
                int n = n_base + wn * 32 + ni * 8 + qcol;
                float v0 = fmaxf(acc[mi][ni][half * 2 + 0] + b1[e * I_DIM + n],     0.f);
                float v1 = fmaxf(acc[mi][ni][half * 2 + 1] + b1[e * I_DIM + n + 1], 0.f);
                __half2 hp = __floats2half2_rn(v0, v1);
                *reinterpret_cast<__half2*>(g_h + pair * I_DIM + n) = hp;
            }
        }
    }
}

// ---------------- GEMM2: out[tok] += wgt * (h @ W2t + b2) ------------------------
__global__ __launch_bounds__(512, 2) void gemm2_kernel(const float* __restrict__ b2,
                                                       float* __restrict__ out) {
    extern __shared__ char smem[];
    const int e = blockIdx.z;
    const int cnt = g_count[e];
    const int m_base = blockIdx.y * 128;
    if (m_base >= cnt) return;
    const int off = e * CAP;
    const int n_base = blockIdx.x * 128;
    const int tid = threadIdx.x;
    const int w = tid >> 5, lane = tid & 31;
    const int wm = w & 3, wn = w >> 2;

    LoadCtx L;
    {
        int rowIdx = tid >> 2;
        int gm = m_base + rowIdx;
        size_t pr = (size_t)(off + ((gm < cnt) ? gm : 0));
        L.aP = (const char*)(g_h + pr * I_DIM);
        size_t rB = ((size_t)e * H_DIM + (n_base + rowIdx)) * I_DIM;
        L.bP = (const char*)(g_w2t + rB);
        L.gOff = (tid & 3) * 32;
        L.sRow = (uint32_t)rowIdx * ROWB + L.gOff;
        L.smem0 = smem_to_u32(smem);
    }

    uint32_t aOff[2], bOff[2];
    {
        int mat = lane >> 3, lr = lane & 7;
        uint32_t kb = (uint32_t)(lane >> 4) * 16;
        #pragma unroll
        for (int mi = 0; mi < 2; mi++)
            aOff[mi] = (uint32_t)(wm * 32 + mi * 16 + ((mat & 1) << 3) + lr) * ROWB + kb;
        #pragma unroll
        for (int nt = 0; nt < 2; nt++)
            bOff[nt] = (uint32_t)(wn * 32 + nt * 16 + ((mat & 1) << 3) + lr) * ROWB + kb;
    }

    float acc[2][4][4] = {};

    const int NC = I_DIM / KC;   // 16
    issue_stage(L, 0, 0);   CP_COMMIT();
    issue_stage(L, 1, KC);  CP_COMMIT();
    for (int c = 0; c < NC; c++) {
        if (c + 2 < NC) CP_WAIT1(); else CP_WAIT0();
        __syncthreads();
        if (c + 2 < NC) { issue_stage(L, (c + 2) % NSTAGE, (c + 2) * KC); CP_COMMIT(); }
        compute_stage(L.smem0 + (c % NSTAGE) * STG_BYTES, aOff, bOff, acc);
    }

    int qrow = lane >> 2, qcol = (lane & 3) * 2;
    #pragma unroll
    for (int mi = 0; mi < 2; mi++) {
        #pragma unroll
        for (int half = 0; half < 2; half++) {
            int row = wm * 32 + mi * 16 + qrow + half * 8;
            int gm = m_base + row;
            if (gm >= cnt) continue;
            int tok = g_list_tok[off + gm];
            float wgt = g_list_w[off + gm];
            float* dst = out + (size_t)tok * H_DIM;
            #pragma unroll
            for (int ni = 0; ni < 4; ni++) {
                int n = n_base + wn * 32 + ni * 8 + qcol;
                atomicAdd(&dst[n],     wgt * (acc[mi][ni][half * 2 + 0] + b2[e * H_DIM + n]));
                atomicAdd(&dst[n + 1], wgt * (acc[mi][ni][half * 2 + 1] + b2[e * H_DIM + n + 1]));
            }
        }
    }
}

// ---------------- launch ----------------------------------------------------------
extern "C" void kernel_launch(void* const* d_in, const int* in_sizes, int n_in,
                              void* d_out, int out_size) {
    const float* x  = (const float*)d_in[0];
    const float* gw = (const float*)d_in[1];
    const float* w1 = (const float*)d_in[2];
    const float* b1 = (const float*)d_in[3];
    const float* w2 = (const float*)d_in[4];
    const float* b2 = (const float*)d_in[5];
    float* out = (float*)d_out;
    float* logits = out + (size_t)T_TOKENS * H_DIM;

    cudaFuncSetAttribute(gemm1_kernel, cudaFuncAttributeMaxDynamicSharedMemorySize, SMEM_BYTES);
    cudaFuncSetAttribute(gemm2_kernel, cudaFuncAttributeMaxDynamicSharedMemorySize, SMEM_BYTES);

    cudaMemsetAsync(out, 0, (size_t)T_TOKENS * H_DIM * sizeof(float), 0);
    void* cnt_ptr = nullptr;
    cudaGetSymbolAddress(&cnt_ptr, g_count);
    cudaMemsetAsync(cnt_ptr, 0, E_NUM * sizeof(int), 0);

    // fused aux: 1024 wconv1 + 1024 wconv2 + 1024 router blocks
    aux_kernel<<<3072, 256>>>(x, gw, w1, w2, logits);

    dim3 g1(I_DIM / 128, T_TOKENS / 128, E_NUM);
    gemm1_kernel<<<g1, 512, SMEM_BYTES>>>(b1);

    dim3 g2(H_DIM / 128, T_TOKENS / 128, E_NUM);
    gemm2_kernel<<<g2, 512, SMEM_BYTES>>>(b2, out);
}

// round 16
// speedup vs baseline: 1.2460x; 1.0012x over previous
#include <cuda_runtime.h>
#include <cuda_fp16.h>
#include <cstdint>
#include <math.h>

#define T_TOKENS 8192
#define H_DIM    512
#define I_DIM    1024
#define E_NUM    8
#define CAP      T_TOKENS                // per-expert capacity
#define KC       64                      // K elems per stage (128B rows)

// ---------------- smem layout -------------------------------------------------
#define ROWB      144
#define TILE_SZ   (128 * ROWB)           // 18432 B
#define OFF_A     0
#define OFF_B     TILE_SZ
#define STG_BYTES (2 * TILE_SZ)          // 36864 B
#define NSTAGE    3
#define SMEM_BYTES (NSTAGE * STG_BYTES)  // 110592 B -> 2 CTAs/SM

// ---------------- PTX helpers ---------------------------------------------------
__device__ __forceinline__ uint32_t smem_to_u32(const void* p) {
    uint32_t a;
    asm("{ .reg .u64 t; cvta.to.shared.u64 t, %1; cvt.u32.u64 %0, t; }" : "=r"(a) : "l"(p));
    return a;
}
__device__ __forceinline__ void cp16(uint32_t s, const void* g) {
    asm volatile("cp.async.cg.shared.global [%0], [%1], 16;" :: "r"(s), "l"(g));
}
#define CP_COMMIT() asm volatile("cp.async.commit_group;" ::: "memory")
#define CP_WAIT1()  asm volatile("cp.async.wait_group 1;" ::: "memory")
#define CP_WAIT0()  asm volatile("cp.async.wait_group 0;" ::: "memory")

__device__ __forceinline__ void ldsm4(uint32_t* r, uint32_t a) {
    asm volatile("ldmatrix.sync.aligned.m8n8.x4.shared.b16 {%0,%1,%2,%3}, [%4];"
        : "=r"(r[0]), "=r"(r[1]), "=r"(r[2]), "=r"(r[3]) : "r"(a));
}
__device__ __forceinline__ void mma_f16(float* c, const uint32_t* a, const uint32_t* b) {
    asm volatile("mma.sync.aligned.m16n8k16.row.col.f32.f16.f16.f32 "
        "{%0,%1,%2,%3}, {%4,%5,%6,%7}, {%8,%9}, {%0,%1,%2,%3};"
        : "+f"(c[0]), "+f"(c[1]), "+f"(c[2]), "+f"(c[3])
        : "r"(a[0]), "r"(a[1]), "r"(a[2]), "r"(a[3]), "r"(b[0]), "r"(b[1]));
}

// ---------------- scratch (device globals) -------------------------------------
__device__ int   g_count[E_NUM];
__device__ int   g_list_tok[E_NUM * CAP];
__device__ float g_list_w[E_NUM * CAP];

__device__ __half g_xh[(size_t)T_TOKENS * H_DIM];
__device__ __half g_w1t[(size_t)E_NUM * I_DIM * H_DIM];   // [e][n=I][k=H]
__device__ __half g_w2t[(size_t)E_NUM * H_DIM * I_DIM];   // [e][n=H][k=I]
__device__ __half g_h[(size_t)E_NUM * CAP * I_DIM];

// ---------------- wconv tile (256-thread variant, for aux kernel) ----------------
__device__ __forceinline__ void wconv_tile256(const float* __restrict__ W,
                                              __half* __restrict__ wh,
                                              int K, int N, int e, int k0, int n0,
                                              float (*s)[65]) {
    int tid = threadIdx.x;
    const float* src = W + (size_t)e * K * N + (size_t)k0 * N + n0;
    int r = tid >> 2, c = tid & 3;
    const float4* row4 = reinterpret_cast<const float4*>(src + (size_t)r * N);
    #pragma unroll
    for (int i = 0; i < 4; i++) {
        int c4 = c + 4 * i;
        float4 v = row4[c4];
        s[r][c4 * 4 + 0] = v.x;
        s[r][c4 * 4 + 1] = v.y;
        s[r][c4 * 4 + 2] = v.z;
        s[r][c4 * 4 + 3] = v.w;
    }
    __syncthreads();
    size_t ob = (size_t)e * N * K + k0;
    #pragma unroll
    for (int q = 0; q < 2; q++) {
        int t = tid + q * 256;
        int kb = t & 7;
        int n  = t >> 3;
        __half hx[8];
        #pragma unroll
        for (int j = 0; j < 8; j++)
            hx[j] = __float2half_rn(s[kb * 8 + j][n]);
        *reinterpret_cast<uint4*>(wh + ob + (size_t)(n0 + n) * K + kb * 8) =
            *reinterpret_cast<uint4*>(hx);
    }
}

// ---------------- wconv tile (512-thread variant, embedded in gemm1) -------------
__device__ __forceinline__ void wconv_tile512(const float* __restrict__ W,
                                              __half* __restrict__ wh,
                                              int K, int N, int e, int k0, int n0,
                                              float (*s)[65]) {
    int tid = threadIdx.x;
    const float* src = W + (size_t)e * K * N + (size_t)k0 * N + n0;
    int r = tid >> 3, c = tid & 7;
    const float4* row4 = reinterpret_cast<const float4*>(src + (size_t)r * N);
    #pragma unroll
    for (int i = 0; i < 2; i++) {
        int c4 = c + 8 * i;           // 0..15
        float4 v = row4[c4];
        s[r][c4 * 4 + 0] = v.x;
        s[r][c4 * 4 + 1] = v.y;
        s[r][c4 * 4 + 2] = v.z;
        s[r][c4 * 4 + 3] = v.w;
    }
    __syncthreads();
    size_t ob = (size_t)e * N * K + k0;
    {
        int kb = tid & 7;
        int n  = tid >> 3;
        __half hx[8];
        #pragma unroll
        for (int j = 0; j < 8; j++)
            hx[j] = __float2half_rn(s[kb * 8 + j][n]);
        *reinterpret_cast<uint4*>(wh + ob + (size_t)(n0 + n) * K + kb * 8) =
            *reinterpret_cast<uint4*>(hx);
    }
    __syncthreads();
}

// ---------------- fused aux kernel: wconv1 | router -----------------------------
// grid.x = 1024 (wconv1) + 1024 (router), 256 threads each.
__global__ void aux_kernel(const float* __restrict__ x,
                           const float* __restrict__ gw,
                           const float* __restrict__ w1,
                           float* __restrict__ logits_out) {
    __shared__ float s[64][65];
    int bid = blockIdx.x;

    if (bid < 1024) {
        // wconv1: K=H_DIM(512), N=I_DIM(1024); tiles 16(n) x 8(k) per expert
        int e = bid >> 7, t = bid & 127;
        int n0 = (t & 15) * 64, k0 = (t >> 4) * 64;
        wconv_tile256(w1, g_w1t, H_DIM, I_DIM, e, k0, n0, s);
        return;
    }

    // ---- router ----
    int rb = bid - 1024;               // 0..1023
    int tid = threadIdx.x;
    int warp = tid >> 5, lane = tid & 31;
    int t = rb * 8 + warp;

    float xr[16];
    #pragma unroll
    for (int j = 0; j < 16; j++) xr[j] = x[(size_t)t * H_DIM + lane + 32 * j];

    #pragma unroll
    for (int j = 0; j < 16; j++)
        g_xh[(size_t)t * H_DIM + lane + 32 * j] = __float2half_rn(xr[j]);

    float lg[E_NUM];
    #pragma unroll
    for (int e = 0; e < E_NUM; e++) {
        float sum = 0.f;
        const float* g = gw + (size_t)e * H_DIM + lane;
        #pragma unroll
        for (int j = 0; j < 16; j++) sum = fmaf(xr[j], g[32 * j], sum);
        #pragma unroll
        for (int o = 16; o; o >>= 1) sum += __shfl_xor_sync(0xffffffffu, sum, o);
        lg[e] = sum;
    }
    if (lane == 0) {
        float m = lg[0];
        #pragma unroll
        for (int e = 1; e < E_NUM; e++) m = fmaxf(m, lg[e]);
        float p[E_NUM], sum = 0.f;
        #pragma unroll
        for (int e = 0; e < E_NUM; e++) { p[e] = expf(lg[e] - m); sum += p[e]; }
        float inv = 1.f / sum;
        #pragma unroll
        for (int e = 0; e < E_NUM; e++) {
            p[e] *= inv;
            logits_out[(size_t)t * E_NUM + e] = lg[e];
        }
        int i0 = 0;
        #pragma unroll
        for (int e = 1; e < E_NUM; e++) if (p[e] > p[i0]) i0 = e;
        int i1 = (i0 == 0) ? 1 : 0;
        #pragma unroll
        for (int e = 0; e < E_NUM; e++) if (e != i1 && e != i0 && p[e] > p[i1]) i1 = e;
        float w0 = p[i0], w1v = p[i1];
        float s2 = w0 + w1v + 1e-20f;
        w0 = (w0 / s2) * 0.5f;
        w1v = (w1v / s2) * 0.5f;
        int p0 = atomicAdd(&g_count[i0], 1);
        g_list_tok[i0 * CAP + p0] = t;  g_list_w[i0 * CAP + p0] = w0;
        int p1 = atomicAdd(&g_count[i1], 1);
        g_list_tok[i1 * CAP + p1] = t;  g_list_w[i1 * CAP + p1] = w1v;
    }
}

// ---------------- GEMM core ------------------------------------------------------
struct LoadCtx {
    const char *aP, *bP;
    uint32_t sRow, gOff, smem0;
};

__device__ __forceinline__ void issue_stage(const LoadCtx& L, int s, int k0elem) {
    uint32_t sb = L.smem0 + s * STG_BYTES + L.sRow;
    size_t gk = (size_t)k0elem * 2 + L.gOff;
    cp16(sb + OFF_A,      L.aP + gk);
    cp16(sb + OFF_A + 16, L.aP + gk + 16);
    cp16(sb + OFF_B,      L.bP + gk);
    cp16(sb + OFF_B + 16, L.bP + gk + 16);
}

__device__ __forceinline__ void compute_stage(uint32_t sb,
        const uint32_t* aOff, const uint32_t* bOff, float acc[2][4][4]) {
    #pragma unroll
    for (int ks = 0; ks < 4; ks++) {
        uint32_t a[2][4], b[2][4];
        #pragma unroll
        for (int mi = 0; mi < 2; mi++)
            ldsm4(a[mi], sb + OFF_A + aOff[mi] + ks * 32);
        #pragma unroll
        for (int nt = 0; nt < 2; nt++)
            ldsm4(b[nt], sb + OFF_B + bOff[nt] + ks * 32);
        #pragma unroll
        for (int mi = 0; mi < 2; mi++) {
            #pragma unroll
            for (int ni = 0; ni < 4; ni++) {
                int nt = ni >> 1, j = ni & 1;
                uint32_t bf[2] = { b[nt][j], b[nt][j + 2] };
                mma_f16(acc[mi][ni], a[mi], bf);
            }
        }
    }
}

// ---------------- GEMM1 (+ embedded wconv2 slice at z==E_NUM) --------------------
__global__ __launch_bounds__(512, 2) void gemm1_kernel(const float* __restrict__ b1,
                                                       const float* __restrict__ w2) {
    extern __shared__ char smem[];

    if (blockIdx.z == E_NUM) {
        // wconv2: K=I_DIM(1024), N=H_DIM(512); 1024 tiles, 512 blocks x 2 tiles
        float (*s)[65] = reinterpret_cast<float(*)[65]>(smem);
        int base = (blockIdx.y * 8 + blockIdx.x) * 2;   // 0..1022
        #pragma unroll
        for (int q = 0; q < 2; q++) {
            int tile = base + q;
            int e = tile >> 7, t = tile & 127;
            int n0 = (t & 7) * 64, k0 = (t >> 3) * 64;
            wconv_tile512(w2, g_w2t, I_DIM, H_DIM, e, k0, n0, s);
        }
        return;
    }

    const int e = blockIdx.z;
    const int cnt = g_count[e];
    const int m_base = blockIdx.y * 128;
    if (m_base >= cnt) return;
    const int off = e * CAP;
    const int n_base = blockIdx.x * 128;
    const int tid = threadIdx.x;
    const int w = tid >> 5, lane = tid & 31;
    const int wm = w & 3, wn = w >> 2;

    LoadCtx L;
    {
        int rowIdx = tid >> 2;
        int gm = m_base + rowIdx;
        int tok = g_list_tok[off + ((gm < cnt) ? gm : 0)];
        L.aP = (const char*)(g_xh + (size_t)tok * H_DIM);
        size_t rB = ((size_t)e * I_DIM + (n_base + rowIdx)) * H_DIM;
        L.bP = (const char*)(g_w1t + rB);
        L.gOff = (tid & 3) * 32;
        L.sRow = (uint32_t)rowIdx * ROWB + L.gOff;
        L.smem0 = smem_to_u32(smem);
    }

    uint32_t aOff[2], bOff[2];
    {
        int mat = lane >> 3, lr = lane & 7;
        uint32_t kb = (uint32_t)(lane >> 4) * 16;
        #pragma unroll
        for (int mi = 0; mi < 2; mi++)
            aOff[mi] = (uint32_t)(wm * 32 + mi * 16 + ((mat & 1) << 3) + lr) * ROWB + kb;
        #pragma unroll
        for (int nt = 0; nt < 2; nt++)
            bOff[nt] = (uint32_t)(wn * 32 + nt * 16 + ((mat & 1) << 3) + lr) * ROWB + kb;
    }

    float acc[2][4][4] = {};

    const int NC = H_DIM / KC;   // 8
    issue_stage(L, 0, 0);   CP_COMMIT();
    issue_stage(L, 1, KC);  CP_COMMIT();
    for (int c = 0; c < NC; c++) {
        if (c + 2 < NC) CP_WAIT1(); else CP_WAIT0();
        __syncthreads();
        if (c + 2 < NC) { issue_stage(L, (c + 2) % NSTAGE, (c + 2) * KC); CP_COMMIT(); }
        compute_stage(L.smem0 + (c % NSTAGE) * STG_BYTES, aOff, bOff, acc);
    }

    int qrow = lane >> 2, qcol = (lane & 3) * 2;
    #pragma unroll
    for (int mi = 0; mi < 2; mi++) {
        #pragma unroll
        for (int half = 0; half < 2; half++) {
            int row = wm * 32 + mi * 16 + qrow + half * 8;
            int gm = m_base + row;
            if (gm >= cnt) continue;
            size_t pair = (size_t)(off + gm);
            #pragma unroll
            for (int ni = 0; ni < 4; ni++) {
                int n = n_base + wn * 32 + ni * 8 + qcol;
                float v0 = fmaxf(acc[mi][ni][half * 2 + 0] + b1[e * I_DIM + n],     0.f);
                float v1 = fmaxf(acc[mi][ni][half * 2 + 1] + b1[e * I_DIM + n + 1], 0.f);
                __half2 hp = __floats2half2_rn(v0, v1);
                *reinterpret_cast<__half2*>(g_h + pair * I_DIM + n) = hp;
            }
        }
    }
}

// ---------------- GEMM2: out[tok] += wgt * (h @ W2t + b2) ------------------------
__global__ __launch_bounds__(512, 2) void gemm2_kernel(const float* __restrict__ b2,
                                                       float* __restrict__ out) {
    extern __shared__ char smem[];
    const int e = blockIdx.z;
    const int cnt = g_count[e];
    const int m_base = blockIdx.y * 128;
    if (m_base >= cnt) return;
    const int off = e * CAP;
    const int n_base = blockIdx.x * 128;
    const int tid = threadIdx.x;
    const int w = tid >> 5, lane = tid & 31;
    const int wm = w & 3, wn = w >> 2;

    LoadCtx L;
    {
        int rowIdx = tid >> 2;
        int gm = m_base + rowIdx;
        size_t pr = (size_t)(off + ((gm < cnt) ? gm : 0));
        L.aP = (const char*)(g_h + pr * I_DIM);
        size_t rB = ((size_t)e * H_DIM + (n_base + rowIdx)) * I_DIM;
        L.bP = (const char*)(g_w2t + rB);
        L.gOff = (tid & 3) * 32;
        L.sRow = (uint32_t)rowIdx * ROWB + L.gOff;
        L.smem0 = smem_to_u32(smem);
    }

    uint32_t aOff[2], bOff[2];
    {
        int mat = lane >> 3, lr = lane & 7;
        uint32_t kb = (uint32_t)(lane >> 4) * 16;
        #pragma unroll
        for (int mi = 0; mi < 2; mi++)
            aOff[mi] = (uint32_t)(wm * 32 + mi * 16 + ((mat & 1) << 3) + lr) * ROWB + kb;
        #pragma unroll
        for (int nt = 0; nt < 2; nt++)
            bOff[nt] = (uint32_t)(wn * 32 + nt * 16 + ((mat & 1) << 3) + lr) * ROWB + kb;
    }

    float acc[2][4][4] = {};

    const int NC = I_DIM / KC;   // 16
    issue_stage(L, 0, 0);   CP_COMMIT();
    issue_stage(L, 1, KC);  CP_COMMIT();
    for (int c = 0; c < NC; c++) {
        if (c + 2 < NC) CP_WAIT1(); else CP_WAIT0();
        __syncthreads();
        if (c + 2 < NC) { issue_stage(L, (c + 2) % NSTAGE, (c + 2) * KC); CP_COMMIT(); }
        compute_stage(L.smem0 + (c % NSTAGE) * STG_BYTES, aOff, bOff, acc);
    }

    int qrow = lane >> 2, qcol = (lane & 3) * 2;
    #pragma unroll
    for (int mi = 0; mi < 2; mi++) {
        #pragma unroll
        for (int half = 0; half < 2; half++) {
            int row = wm * 32 + mi * 16 + qrow + half * 8;
            int gm = m_base + row;
            if (gm >= cnt) continue;
            int tok = g_list_tok[off + gm];
            float wgt = g_list_w[off + gm];
            float* dst = out + (size_t)tok * H_DIM;
            #pragma unroll
            for (int ni = 0; ni < 4; ni++) {
                int n = n_base + wn * 32 + ni * 8 + qcol;
                atomicAdd(&dst[n],     wgt * (acc[mi][ni][half * 2 + 0] + b2[e * H_DIM + n]));
                atomicAdd(&dst[n + 1], wgt * (acc[mi][ni][half * 2 + 1] + b2[e * H_DIM + n + 1]));
            }
        }
    }
}

// ---------------- launch ----------------------------------------------------------
extern "C" void kernel_launch(void* const* d_in, const int* in_sizes, int n_in,
                              void* d_out, int out_size) {
    const float* x  = (const float*)d_in[0];
    const float* gw = (const float*)d_in[1];
    const float* w1 = (const float*)d_in[2];
    const float* b1 = (const float*)d_in[3];
    const float* w2 = (const float*)d_in[4];
    const float* b2 = (const float*)d_in[5];
    float* out = (float*)d_out;
    float* logits = out + (size_t)T_TOKENS * H_DIM;

    cudaFuncSetAttribute(gemm1_kernel, cudaFuncAttributeMaxDynamicSharedMemorySize, SMEM_BYTES);
    cudaFuncSetAttribute(gemm2_kernel, cudaFuncAttributeMaxDynamicSharedMemorySize, SMEM_BYTES);

    cudaMemsetAsync(out, 0, (size_t)T_TOKENS * H_DIM * sizeof(float), 0);
    void* cnt_ptr = nullptr;
    cudaGetSymbolAddress(&cnt_ptr, g_count);
    cudaMemsetAsync(cnt_ptr, 0, E_NUM * sizeof(int), 0);

    // fused aux: 1024 wconv1 + 1024 router blocks
    aux_kernel<<<2048, 256>>>(x, gw, w1, logits);

    // gemm1 + embedded wconv2 slice (z == E_NUM)
    dim3 g1(I_DIM / 128, T_TOKENS / 128, E_NUM + 1);
    gemm1_kernel<<<g1, 512, SMEM_BYTES>>>(b1, w2);

    dim3 g2(H_DIM / 128, T_TOKENS / 128, E_NUM);
    gemm2_kernel<<<g2, 512, SMEM_BYTES>>>(b2, out);
}